// round 12
// baseline (speedup 1.0000x reference)
#include <cuda_runtime.h>
#include <cuda_bf16.h>
#include <cuda_fp16.h>
#include <cuda_fp8.h>
#include <cstdint>

#define HH 150
#define APITCH 152          // g_A/g_B row pitch (floats)

#define EPITCH 392          // bf16 E row pitch (u32 words) — k1 only
#define EP2 388             // f16 E row pitch (u32 words) — k2, k32-interleaved
#define H1P 50              // h1 row pitch in u32 words (e4m3, K padded 192)
#define WABPITCH 36         // k1 weight row pitch (u32 words)

// fp8 packed-fragment W blob: per k32-step: 32 lanes * 44 words (40 used)
#define PKS8 1408
#define SLAB8_W (2 * PKS8)          // 2 ks32 per slab = 11264 B
#define W1C8_WORDS (24 * PKS8)      // 24 ks32 (K=768)
#define W28_WORDS  (6 * PKS8)       // 6 ks32 (K=160 pad 192)
#define NSLOT 15                    // 12 layer-1 + 3 layer-2 slabs

// ---------------- device scratch ----------------
__device__ __align__(16) uint32_t      g_Ebf[1536 * EPITCH];   // bf16 (k1)
__device__ __align__(16) uint32_t      g_Ef[1536 * EP2];       // f16 (k2)
__device__ __align__(16) __nv_bfloat16 g_wabT[12 * 320 * 72];
__device__ __align__(16) uint32_t      g_w1c8[W1C8_WORDS];
__device__ __align__(16) uint32_t      g_w28[W28_WORDS];
__device__ __align__(16) float g_A[1536 * APITCH];
__device__ __align__(16) float g_B[1536 * APITCH];
__device__ float g_S[8 * 192 * 192];
__device__ float g_S2[8 * 192 * 192];

// ---------------- helpers ----------------
__device__ __forceinline__ uint32_t smem_u32(const void* p) {
    uint32_t a;
    asm("{ .reg .u64 t; cvta.to.shared.u64 t, %1; cvt.u32.u64 %0, t; }" : "=r"(a) : "l"(p));
    return a;
}
__device__ __forceinline__ uint32_t packbf(float lo, float hi) {
    uint32_t d; asm("cvt.rn.bf16x2.f32 %0, %1, %2;" : "=r"(d) : "f"(hi), "f"(lo)); return d;
}
__device__ __forceinline__ uint32_t packh2(float lo, float hi) {
    __half2 h = __floats2half2_rn(lo, hi);
    return *reinterpret_cast<uint32_t*>(&h);
}
// two f16x2 products -> 4 e4m3 packed in one u32 (low byte = lowest k)
__device__ __forceinline__ uint32_t prod8(uint32_t ex0, uint32_t ex1,
                                          uint32_t ej0, uint32_t ej1) {
    uint32_t p0, p1; unsigned short c0, c1;
    asm("mul.rn.f16x2 %0, %1, %2;" : "=r"(p0) : "r"(ex0), "r"(ej0));
    asm("mul.rn.f16x2 %0, %1, %2;" : "=r"(p1) : "r"(ex1), "r"(ej1));
    asm("cvt.rn.satfinite.e4m3x2.f16x2 %0, %1;" : "=h"(c0) : "r"(p0));
    asm("cvt.rn.satfinite.e4m3x2.f16x2 %0, %1;" : "=h"(c1) : "r"(p1));
    return (uint32_t)c0 | ((uint32_t)c1 << 16);
}
__device__ __forceinline__ unsigned short cvt8x2(float hi, float lo) {
    unsigned short d;
    asm("cvt.rn.satfinite.e4m3x2.f32 %0, %1, %2;" : "=h"(d) : "f"(hi), "f"(lo));
    return d;
}
__device__ __forceinline__ void mma16816(float* d, const uint32_t* a, const uint32_t* b,
                                         const float* c) {
    asm volatile(
        "mma.sync.aligned.m16n8k16.row.col.f32.bf16.bf16.f32 "
        "{%0,%1,%2,%3}, {%4,%5,%6,%7}, {%8,%9}, {%10,%11,%12,%13};"
        : "=f"(d[0]), "=f"(d[1]), "=f"(d[2]), "=f"(d[3])
        : "r"(a[0]), "r"(a[1]), "r"(a[2]), "r"(a[3]), "r"(b[0]), "r"(b[1]),
          "f"(c[0]), "f"(c[1]), "f"(c[2]), "f"(c[3]));
}
__device__ __forceinline__ void mma16832(float* d, const uint32_t* a, const uint32_t* b,
                                         const float* c) {
    asm volatile(
        "mma.sync.aligned.m16n8k32.row.col.f32.e4m3.e4m3.f32 "
        "{%0,%1,%2,%3}, {%4,%5,%6,%7}, {%8,%9}, {%10,%11,%12,%13};"
        : "=f"(d[0]), "=f"(d[1]), "=f"(d[2]), "=f"(d[3])
        : "r"(a[0]), "r"(a[1]), "r"(a[2]), "r"(a[3]), "r"(b[0]), "r"(b[1]),
          "f"(c[0]), "f"(c[1]), "f"(c[2]), "f"(c[3]));
}
#define MBAR_INIT(mb, cnt) asm volatile("mbarrier.init.shared.b64 [%0], %1;" :: "r"((uint32_t)(mb)), "r"((uint32_t)(cnt)) : "memory")
#define MBAR_EXPECT_TX(mb, n) asm volatile("mbarrier.arrive.expect_tx.shared.b64 _, [%0], %1;" :: "r"((uint32_t)(mb)), "r"((uint32_t)(n)) : "memory")
#define MBAR_ARRIVE(mb) asm volatile("mbarrier.arrive.release.cta.shared::cta.b64 _, [%0];" :: "r"((uint32_t)(mb)) : "memory")
#define FENCE_ASYNC() asm volatile("fence.proxy.async.shared::cta;" ::: "memory")
#define NBAR(id, cnt) asm volatile("bar.sync %0, %1;" :: "r"(id), "r"(cnt) : "memory")
#define MBAR_WAIT(mb, ph) do { \
    uint32_t _m = (uint32_t)(mb); uint32_t _p = (uint32_t)(ph); uint32_t _d; \
    asm volatile("{\n\t.reg .pred p;\n\tmbarrier.try_wait.parity.acquire.cta.shared::cta.b64 p, [%1], %2;\n\tselp.b32 %0, 1, 0, p;\n\t}" \
        : "=r"(_d) : "r"(_m), "r"(_p) : "memory"); \
    if (!_d) { \
        asm volatile("{\n\t.reg .pred P1;\n\tWL_%=:\n\tmbarrier.try_wait.parity.acquire.cta.shared::cta.b64 P1, [%0], %1, 0x989680;\n\t@P1 bra.uni WD_%=;\n\tbra.uni WL_%=;\n\tWD_%=:\n\t}" \
            :: "r"(_m), "r"(_p) : "memory"); \
    } } while (0)
__device__ __forceinline__ void bulk_g2s(uint32_t dst, const void* src, uint32_t bytes, uint32_t mbar) {
    asm volatile("cp.async.bulk.shared::cta.global.mbarrier::complete_tx::bytes [%0], [%1], %2, [%3];"
        :: "r"(dst), "l"(src), "r"(bytes), "r"(mbar) : "memory");
}

// ---------------- merged prep ----------------
#define PE_N  (1536 * EPITCH)
#define PE2_N (1536 * EP2)
#define WAB_N (12 * 320 * 72)
__global__ void kprep(const float* __restrict__ E,
                      const float* __restrict__ W1, const float* __restrict__ W2) {
    int idx = blockIdx.x * 256 + threadIdx.x;
    if (idx < PE_N) {
        // bf16 E, k16-interleaved (k1)
        int r = idx / EPITCH, pos = idx % EPITCH;
        int g = pos >> 3, wi = pos & 7, q = wi >> 1, h = wi & 1;
        int kw = g * 8 + q + 4 * h;
        uint32_t v = 0;
        if (kw < 384) {
            float2 e = *reinterpret_cast<const float2*>(E + (size_t)r * 768 + 2 * kw);
            v = packbf(e.x, e.y);
        }
        g_Ebf[idx] = v;
    } else if (idx < PE_N + PE2_N) {
        // f16 E, k32-interleaved (k2): group of 16 words; pos np: qq=np>>2, c=np&3
        int t = idx - PE_N;
        int r = t / EP2, pos = t % EP2;
        int g = pos >> 4, np = pos & 15;
        int qq = np >> 2, c = np & 3;
        int wlo = (c < 2) ? (2 * qq + c) : (8 + 2 * qq + (c - 2));
        int kw = g * 16 + wlo;
        uint32_t v = 0;
        if (kw < 384) {
            float2 e = *reinterpret_cast<const float2*>(E + (size_t)r * 768 + 2 * kw);
            v = packh2(e.x, e.y);
        }
        g_Ef[t] = v;
    } else if (idx < PE_N + PE2_N + WAB_N) {
        int t = idx - PE_N - PE2_N;
        int c = t / (320 * 72), rem = t % (320 * 72);
        int n = rem / 72, kk = rem % 72;
        float v = 0.f;
        if (kk < 64) {
            int kg = c * 64 + kk;
            if (n < 160) { if (n < HH) v = W1[(size_t)kg * HH + n]; }
            else { int h = n - 160; if (h < HH) v = W1[(size_t)(768 + kg) * HH + h]; }
        }
        g_wabT[t] = __float2bfloat16(v);
    } else if (idx < PE_N + PE2_N + WAB_N + W1C8_WORDS + W28_WORDS) {
        int t = idx - PE_N - PE2_N - WAB_N;
        bool isW2 = (t >= W1C8_WORDS);
        int r = isW2 ? (t - W1C8_WORDS) : t;
        int ks = r / PKS8, r1 = r % PKS8;
        int lane = r1 / 44, ws = r1 % 44;
        uint32_t v = 0;
        if (ws < 40) {
            int nhh = ws / 20, w2 = ws % 20, p = w2 >> 2, cc = w2 & 3;
            int gq = lane >> 2, qq = lane & 3;
            int nb = nhh * 10 + 2 * p + (cc >> 1);
            int reg = cc & 1;
            int n = nb * 8 + gq;
            int k0 = ks * 32 + qq * 4 + reg * 16;
            unsigned char by[4];
#pragma unroll
            for (int b = 0; b < 4; b++) {
                float vv = 0.f;
                int k = k0 + b;
                if (n < HH) {
                    if (isW2) { if (k < HH) vv = W2[(size_t)k * HH + n]; }
                    else      { vv = W1[(size_t)(1536 + k) * HH + n]; }
                }
                by[b] = (unsigned char)__nv_cvt_float_to_fp8(vv, __NV_SATFINITE, __NV_E4M3);
            }
            v = (uint32_t)by[0] | ((uint32_t)by[1] << 8) |
                ((uint32_t)by[2] << 16) | ((uint32_t)by[3] << 24);
        }
        if (isW2) g_w28[r] = v; else g_w1c8[r] = v;
    }
}

// ---------------- k1: seeds GEMM -> g_A,g_B (bf16, unchanged) ----------------
#define K1_E_BYTES (32 * EPITCH * 4)
#define K1_W_BYTES (320 * WABPITCH * 4)
#define K1_BAR_OFF (K1_E_BYTES + 2 * K1_W_BYTES)
#define K1_SMEM    (K1_BAR_OFF + 64)

__global__ __launch_bounds__(256, 1)
void k1_mma(const float* __restrict__ b1) {
    extern __shared__ __align__(128) char smem[];
    uint32_t* sE = (uint32_t*)smem;
    uint32_t* sW[2] = { (uint32_t*)(smem + K1_E_BYTES),
                        (uint32_t*)(smem + K1_E_BYTES + K1_W_BYTES) };
    const uint32_t barE = smem_u32(smem + K1_BAR_OFF);
    const uint32_t barW[2] = { barE + 8, barE + 16 };
    const int tid = threadIdx.x, w = tid >> 5, lane = tid & 31;
    const int gq = lane >> 2, qq = lane & 3;
    const int r0 = blockIdx.x * 32;

    if (tid == 0) {
        MBAR_INIT(barE, 1); MBAR_INIT(barW[0], 1); MBAR_INIT(barW[1], 1);
        FENCE_ASYNC();
        MBAR_EXPECT_TX(barE, K1_E_BYTES);
        bulk_g2s(smem_u32(sE), g_Ebf + (size_t)r0 * EPITCH, K1_E_BYTES, barE);
        MBAR_EXPECT_TX(barW[0], K1_W_BYTES);
        bulk_g2s(smem_u32(sW[0]), g_wabT, K1_W_BYTES, barW[0]);
        MBAR_EXPECT_TX(barW[1], K1_W_BYTES);
        bulk_g2s(smem_u32(sW[1]), g_wabT + (size_t)320 * 72, K1_W_BYTES, barW[1]);
    }
    __syncthreads();
    MBAR_WAIT(barE, 0);

    float acc[2][5][4];
#pragma unroll
    for (int t = 0; t < 2; t++)
#pragma unroll
        for (int l = 0; l < 5; l++)
#pragma unroll
            for (int u = 0; u < 4; u++) acc[t][l][u] = 0.f;

    const uint32_t* e0p = sE + (size_t)gq * EPITCH;
    const uint32_t* e1p = e0p + 8 * EPITCH;
    const uint32_t* e2p = e0p + 16 * EPITCH;
    const uint32_t* e3p = e0p + 24 * EPITCH;

    for (int c = 0; c < 12; c++) {
        MBAR_WAIT(barW[c & 1], (c >> 1) & 1);
        const uint32_t* Wb = sW[c & 1];
#pragma unroll
        for (int ks = 0; ks < 4; ks++) {
            int kb = c * 32 + ks * 8 + 2 * qq;
            uint2 e0 = *(const uint2*)(e0p + kb);
            uint2 e1 = *(const uint2*)(e1p + kb);
            uint2 e2 = *(const uint2*)(e2p + kb);
            uint2 e3 = *(const uint2*)(e3p + kb);
            uint32_t a0[4] = { e0.x, e1.x, e0.y, e1.y };
            uint32_t a1[4] = { e2.x, e3.x, e2.y, e3.y };
#pragma unroll
            for (int l = 0; l < 5; l++) {
                int nrow = (w * 5 + l) * 8 + gq;
                uint32_t b[2] = { Wb[nrow * WABPITCH + ks * 8 + qq],
                                  Wb[nrow * WABPITCH + ks * 8 + qq + 4] };
                mma16816(acc[0][l], a0, b, acc[0][l]);
                mma16816(acc[1][l], a1, b, acc[1][l]);
            }
        }
        __syncthreads();
        if (tid == 0 && c + 2 < 12) {
            MBAR_EXPECT_TX(barW[c & 1], K1_W_BYTES);
            bulk_g2s(smem_u32(sW[c & 1]), g_wabT + (size_t)(c + 2) * 320 * 72,
                     K1_W_BYTES, barW[c & 1]);
        }
    }

#pragma unroll
    for (int t = 0; t < 2; t++)
#pragma unroll
        for (int l = 0; l < 5; l++) {
            int n0 = (w * 5 + l) * 8 + 2 * qq;
            int ra = r0 + 16 * t + gq, rb = ra + 8;
#pragma unroll
            for (int u = 0; u < 4; u++) {
                int row = (u < 2) ? ra : rb;
                int n = n0 + (u & 1);
                float v = acc[t][l][u];
                if (n < 160) { if (n < HH) g_A[(size_t)row * APITCH + n] = v + __ldg(b1 + n); }
                else { int h = n - 160; if (h < HH) g_B[(size_t)row * APITCH + h] = v; }
            }
        }
}

// ---------------- k2: fused pair MLP, FP8, 2 CTAs/SM, 4-deep W ring ----------------
// Compact grid (208, 8). 192 thr = 6 warps: mh=w>>1 (m32), nh=w&1 (n80 half). Tile 12x8.
#define K2_EI_OFF   0                                  // 12*388*4 = 18624
#define K2_EJ_OFF   18624                              // 8*388*4  = 12416
#define K2_W_OFF    31040                              // 4 x 11264 = 45056
#define K2_H1_OFF   76096                              // 96*50*4 = 19200
#define K2_BW_OFF   95296                              // b2|W3: 1216
#define K2_BAR_OFF  96512
#define K2_SMEM     (K2_BAR_OFF + 128)                 // 96640

__global__ __launch_bounds__(192, 2)
void k2_mma(const float* __restrict__ b2,
            const float* __restrict__ W3) {
    const int bz = blockIdx.y;
    const int x = blockIdx.x;
    const int cumt[16] = {0,2,5,10,16,24,33,44,56,70,85,102,120,140,161,184};
    int ti = 0;
#pragma unroll
    for (int t = 1; t < 16; t++)
        if (cumt[t] <= x) ti = t;
    const int tj = x - cumt[ti];

    extern __shared__ __align__(128) char smem[];
    uint32_t* sEi = (uint32_t*)(smem + K2_EI_OFF);
    uint32_t* sEj = (uint32_t*)(smem + K2_EJ_OFF);
    uint32_t* sWr = (uint32_t*)(smem + K2_W_OFF);      // ring: 4 x SLAB8_W
    uint32_t* sH1 = (uint32_t*)(smem + K2_H1_OFF);
    char*     sH1c = smem + K2_H1_OFF;
    float*    sB2 = (float*)(smem + K2_BW_OFF);
    float*    sW3 = sB2 + 152;
    const uint32_t barE  = smem_u32(smem + K2_BAR_OFF);
    const uint32_t barW0 = barE + 8;    // barW[b] = barW0 + 8b
    const uint32_t barC0 = barE + 40;   // barC[b] = barC0 + 8b
    const int tid = threadIdx.x, w = tid >> 5, lane = tid & 31;
    const int mh = w >> 1, nh = w & 1;
    const int gq = lane >> 2, qq = lane & 3;

    if (tid == 0) {
        MBAR_INIT(barE, 1);
#pragma unroll
        for (int b = 0; b < 4; b++) { MBAR_INIT(barW0 + 8 * b, 1); MBAR_INIT(barC0 + 8 * b, 6); }
        FENCE_ASYNC();
        MBAR_EXPECT_TX(barE, (12 + 8) * EP2 * 4);
        bulk_g2s(smem_u32(sEi), g_Ef + ((size_t)bz * 192 + ti * 12) * EP2, 12 * EP2 * 4, barE);
        bulk_g2s(smem_u32(sEj), g_Ef + ((size_t)bz * 192 + tj * 8) * EP2, 8 * EP2 * 4, barE);
#pragma unroll
        for (int f = 0; f < 4; f++) {
            MBAR_EXPECT_TX(barW0 + 8 * f, SLAB8_W * 4);
            bulk_g2s(smem_u32(sWr + f * SLAB8_W), g_w1c8 + (size_t)f * SLAB8_W,
                     SLAB8_W * 4, barW0 + 8 * f);
        }
    }
    // stage b2/W3; zero h1 tail words {37, 39, 40..47} per row (k bytes 152..191)
    for (int idx = tid; idx < 304; idx += 192) {
        if (idx < 152) sB2[idx] = (idx < HH) ? b2[idx] : 0.f;
        else { int h = idx - 152; sW3[h] = (h < HH) ? W3[h] : 0.f; }
    }
    for (int idx = tid; idx < 96 * 10; idx += 192) {
        int row = idx / 10, z = idx % 10;
        int wd = (z == 0) ? 37 : (z == 1) ? 39 : (38 + z);   // 37,39,40..47
        sH1[(size_t)row * H1P + wd] = 0;
    }
    __syncthreads();
    MBAR_WAIT(barE, 0);

    float acc[2][10][4];
#pragma unroll
    for (int t = 0; t < 2; t++)
#pragma unroll
        for (int l = 0; l < 10; l++)
#pragma unroll
            for (int u = 0; u < 4; u++) acc[t][l][u] = 0.f;

    const uint32_t* eI0 = sEi + (size_t)(4 * mh + 0) * EP2;
    const uint32_t* eI1 = sEi + (size_t)(4 * mh + 1) * EP2;
    const uint32_t* eI2 = sEi + (size_t)(4 * mh + 2) * EP2;
    const uint32_t* eI3 = sEi + (size_t)(4 * mh + 3) * EP2;
    const uint32_t* eJp = sEj + (size_t)gq * EP2;
    const int bw_off = lane * 44 + nh * 20;
    const bool full_n = (nh == 0);   // nh==1 skips all-zero n-block 19

#define MMA_NBLOCKS8(ACC, a0, a1, bp) do { \
        _Pragma("unroll") \
        for (int m = 0; m < 4; m++) { \
            uint4 bb = *(const uint4*)((bp) + m * 4); \
            uint32_t b0[2] = { bb.x, bb.y }; \
            uint32_t b1r[2] = { bb.z, bb.w }; \
            mma16832(ACC[0][2 * m],     a0, b0,  ACC[0][2 * m]); \
            mma16832(ACC[1][2 * m],     a1, b0,  ACC[1][2 * m]); \
            mma16832(ACC[0][2 * m + 1], a0, b1r, ACC[0][2 * m + 1]); \
            mma16832(ACC[1][2 * m + 1], a1, b1r, ACC[1][2 * m + 1]); \
        } \
        { \
            uint4 bb = *(const uint4*)((bp) + 16); \
            uint32_t b0[2] = { bb.x, bb.y }; \
            mma16832(ACC[0][8], a0, b0, ACC[0][8]); \
            mma16832(ACC[1][8], a1, b0, ACC[1][8]); \
            if (full_n) { \
                uint32_t b1r[2] = { bb.z, bb.w }; \
                mma16832(ACC[0][9], a0, b1r, ACC[0][9]); \
                mma16832(ACC[1][9], a1, b1r, ACC[1][9]); \
            } \
        } \
    } while (0)

    // ---- layer 1: 12 slabs of 2 ks32 through the 4-buffer ring ----
    for (int f = 0; f < 12; f++) {
        const int buf = f & 3;
        const uint32_t bw = barW0 + 8 * buf, bc = barC0 + 8 * buf;
        MBAR_WAIT(bw, (f >> 2) & 1);
        const uint32_t* Wb = sWr + buf * SLAB8_W;
#pragma unroll
        for (int ks = 0; ks < 2; ks++) {
            int base = (f * 2 + ks) * 16 + 4 * qq;
            uint4 ej = *(const uint4*)(eJp + base);
            uint4 e0 = *(const uint4*)(eI0 + base);
            uint4 e1 = *(const uint4*)(eI1 + base);
            uint4 e2 = *(const uint4*)(eI2 + base);
            uint4 e3 = *(const uint4*)(eI3 + base);
            uint32_t a0[4] = { prod8(e0.x, e0.y, ej.x, ej.y),
                               prod8(e1.x, e1.y, ej.x, ej.y),
                               prod8(e0.z, e0.w, ej.z, ej.w),
                               prod8(e1.z, e1.w, ej.z, ej.w) };
            uint32_t a1[4] = { prod8(e2.x, e2.y, ej.x, ej.y),
                               prod8(e3.x, e3.y, ej.x, ej.y),
                               prod8(e2.z, e2.w, ej.z, ej.w),
                               prod8(e3.z, e3.w, ej.z, ej.w) };
            const uint32_t* bp = Wb + ks * PKS8 + bw_off;
            MMA_NBLOCKS8(acc, a0, a1, bp);
        }
        __syncwarp();
        if (lane == 0) MBAR_ARRIVE(bc);
        if (w == 0 && lane == 0) {
            MBAR_WAIT(bc, (f >> 2) & 1);
            int nf = f + 4;
            if (nf < NSLOT) {
                const uint32_t* src = (nf < 12) ? g_w1c8 + (size_t)nf * SLAB8_W
                                                : g_w28 + (size_t)(nf - 12) * SLAB8_W;
                MBAR_EXPECT_TX(bw, SLAB8_W * 4);
                bulk_g2s(smem_u32(sWr + buf * SLAB8_W), src, SLAB8_W * 4, bw);
            }
        }
    }

    // ---- epilogue 1: + seeds (L2 gmem), ReLU, e4m3 -> sH1 (k32-interleaved) ----
    {
        const float* Bj = g_B + ((size_t)bz * 192 + tj * 8 + gq) * APITCH;
#pragma unroll
        for (int t = 0; t < 2; t++) {
            const float* A0 = g_A + ((size_t)bz * 192 + ti * 12 + 4 * mh + 2 * t) * APITCH;
            const float* A1 = A0 + APITCH;
#pragma unroll
            for (int l = 0; l < 10; l++) {
                if (l == 9 && !full_n) break;
                int nbg = nh * 10 + l;
                int h0 = nbg * 8 + 2 * qq;
                float v0 = 0.f, v1 = 0.f, v2 = 0.f, v3 = 0.f;
                if (h0 < HH) {
                    float2 a0v = *(const float2*)(A0 + h0);
                    float2 a1v = *(const float2*)(A1 + h0);
                    float2 bjv = *(const float2*)(Bj + h0);
                    v0 = fmaxf(acc[t][l][0] + a0v.x + bjv.x, 0.f);
                    v1 = fmaxf(acc[t][l][1] + a0v.y + bjv.y, 0.f);
                    v2 = fmaxf(acc[t][l][2] + a1v.x + bjv.x, 0.f);
                    v3 = fmaxf(acc[t][l][3] + a1v.y + bjv.y, 0.f);
                }
                unsigned short ca = cvt8x2(v1, v0);
                unsigned short cb = cvt8x2(v3, v2);
                int wq = h0 >> 2, gg = wq >> 3, wlo = wq & 7;
                int pos = (wlo < 4) ? (2 * wlo) : (2 * (wlo - 4) + 1);
                int boff = (gg * 8 + pos) * 4 + (h0 & 2);
                *(unsigned short*)(sH1c + (size_t)(32 * mh + 16 * t + gq) * 200 + boff) = ca;
                *(unsigned short*)(sH1c + (size_t)(32 * mh + 16 * t + 8 + gq) * 200 + boff) = cb;
            }
        }
    }
    NBAR(1 + mh, 64);          // nh-pair exchange of h1 halves

    // ---- layer 2: slots 12..14 (2 ks32 each, K padded 192) ----
    float ac2[2][10][4];
#pragma unroll
    for (int t = 0; t < 2; t++)
#pragma unroll
        for (int l = 0; l < 10; l++)
#pragma unroll
            for (int u = 0; u < 4; u++) ac2[t][l][u] = 0.f;

    const uint32_t* h0p = sH1 + (size_t)(32 * mh + gq) * H1P;
    const uint32_t* h1p = h0p + 8 * H1P;
    const uint32_t* h2p = h0p + 16 * H1P;
    const uint32_t* h3p = h0p + 24 * H1P;

#pragma unroll
    for (int f = 12; f < 15; f++) {
        const int buf = f & 3;
        const uint32_t bw = barW0 + 8 * buf;
        MBAR_WAIT(bw, (f >> 2) & 1);
        const uint32_t* Wb = sWr + buf * SLAB8_W;
#pragma unroll
        for (int ks = 0; ks < 2; ks++) {
            int kb = ((f - 12) * 2 + ks) * 8 + 2 * qq;
            uint2 x0 = *(const uint2*)(h0p + kb);
            uint2 x1 = *(const uint2*)(h1p + kb);
            uint2 x2 = *(const uint2*)(h2p + kb);
            uint2 x3 = *(const uint2*)(h3p + kb);
            uint32_t a0[4] = { x0.x, x1.x, x0.y, x1.y };
            uint32_t a1[4] = { x2.x, x3.x, x2.y, x3.y };
            const uint32_t* bp = Wb + ks * PKS8 + bw_off;
            MMA_NBLOCKS8(ac2, a0, a1, bp);
        }
    }

    // ---- epilogue 2: +b2, ReLU, dot W3; partials to g_S / g_S2 ----
    float sp[2][2] = { {0.f, 0.f}, {0.f, 0.f} };
#pragma unroll
    for (int t = 0; t < 2; t++)
#pragma unroll
        for (int l = 0; l < 10; l++) {
            if (l == 9 && !full_n) break;
            int h0 = (nh * 10 + l) * 8 + 2 * qq;
            if (h0 < HH) {
                float2 bv = *(const float2*)(sB2 + h0);
                float2 wv = *(const float2*)(sW3 + h0);
                sp[t][0] += fmaxf(ac2[t][l][0] + bv.x, 0.f) * wv.x
                          + fmaxf(ac2[t][l][1] + bv.y, 0.f) * wv.y;
                sp[t][1] += fmaxf(ac2[t][l][2] + bv.x, 0.f) * wv.x
                          + fmaxf(ac2[t][l][3] + bv.y, 0.f) * wv.y;
            }
        }
#pragma unroll
    for (int t = 0; t < 2; t++)
#pragma unroll
        for (int s = 0; s < 2; s++) {
            sp[t][s] += __shfl_xor_sync(0xffffffffu, sp[t][s], 1);
            sp[t][s] += __shfl_xor_sync(0xffffffffu, sp[t][s], 2);
        }
    if (qq == 0) {
        float* dst = full_n ? g_S2 : g_S;
#pragma unroll
        for (int t = 0; t < 2; t++)
#pragma unroll
            for (int s = 0; s < 2; s++) {
                int r = 32 * mh + 16 * t + 8 * s + gq;
                int ip = ti * 12 + (r >> 3), jp = tj * 8 + (r & 7);
                if (jp < ip)
                    dst[((size_t)bz * 192 + ip) * 192 + jp] = sp[t][s];
            }
    }
}

// ---------------- k3: tril softmax (sums the two partial-score arrays) ----------------
__global__ void k3_softmax(float* __restrict__ out, const float* __restrict__ b3) {
    const int i = blockIdx.x, b = blockIdx.y, j = threadIdx.x;
    const float b3v = __ldg(b3);
    float val;
    if (j < i) {
        size_t idx = ((size_t)b * 192 + i) * 192 + j;
        val = g_S[idx] + g_S2[idx] + b3v;
    } else if (j == i) val = 0.f;
    else               val = -1e30f;

    __shared__ float red[6];
    float m = val;
#pragma unroll
    for (int o = 16; o; o >>= 1) m = fmaxf(m, __shfl_xor_sync(0xffffffffu, m, o));
    if ((j & 31) == 0) red[j >> 5] = m;
    __syncthreads();
    float M = fmaxf(fmaxf(fmaxf(red[0], red[1]), fmaxf(red[2], red[3])), fmaxf(red[4], red[5]));
    __syncthreads();
    float e = (j <= i) ? expf(val - M) : 0.f;
    float s = e;
#pragma unroll
    for (int o = 16; o; o >>= 1) s += __shfl_xor_sync(0xffffffffu, s, o);
    if ((j & 31) == 0) red[j >> 5] = s;
    __syncthreads();
    float S = red[0] + red[1] + red[2] + red[3] + red[4] + red[5];
    out[((size_t)b * 192 + i) * 192 + j] = (j <= i) ? (e / S) : -1000.0f;
}

// ---------------------------------------------------------------------------
extern "C" void kernel_launch(void* const* d_in, const int* in_sizes, int n_in,
                              void* d_out, int out_size) {
    const float* E  = (const float*)d_in[0];
    const float* W1 = (const float*)d_in[1];
    const float* b1 = (const float*)d_in[2];
    const float* W2 = (const float*)d_in[3];
    const float* b2 = (const float*)d_in[4];
    const float* W3 = (const float*)d_in[5];
    const float* b3 = (const float*)d_in[6];
    float* out = (float*)d_out;

    cudaFuncSetAttribute(k1_mma, cudaFuncAttributeMaxDynamicSharedMemorySize, K1_SMEM);
    cudaFuncSetAttribute(k2_mma, cudaFuncAttributeMaxDynamicSharedMemorySize, K2_SMEM);

    const int prep_n = PE_N + PE2_N + WAB_N + W1C8_WORDS + W28_WORDS;
    kprep<<<(prep_n + 255) / 256, 256>>>(E, W1, W2);
    k1_mma<<<48, 256, K1_SMEM>>>(b1);
    k2_mma<<<dim3(208, 8), 192, K2_SMEM>>>(b2, W3);
    k3_softmax<<<dim3(192, 8), 192>>>(out, b3);
}

// round 13
// speedup vs baseline: 1.1564x; 1.1564x over previous
#include <cuda_runtime.h>
#include <cuda_bf16.h>
#include <cstdint>

#define HH 150
#define APITCH 152          // g_A/g_B row pitch (floats)

#define EPITCH 392          // E row pitch in u32 words
#define H1PITCH 88          // h1 row pitch in u32 words
#define WABPITCH 36         // k1 weight row pitch (u32 words)

// Packed-fragment W blob geometry: per k16-step: 32 lanes * 44 words
#define PKS 1408
#define W1C_WORDS (48 * PKS)
#define W2_WORDS  (10 * PKS)
#define SLAB_W (2 * PKS)    // 2 ks per fetch slab (11264 B)
#define SLOTS_PER_TILE 29   // 24 W1c + 5 W2
#define NTILES 1664
#define K2_GRID 296

// ---------------- device scratch ----------------
__device__ __align__(16) uint32_t      g_Ebf[1536 * EPITCH];
__device__ __align__(16) __nv_bfloat16 g_wabT[12 * 320 * 72];
__device__ __align__(16) uint32_t      g_w1cP[W1C_WORDS];
__device__ __align__(16) uint32_t      g_w2P[W2_WORDS];
__device__ __align__(16) float g_A[1536 * APITCH];
__device__ __align__(16) float g_B[1536 * APITCH];
__device__ float g_S[8 * 192 * 192];
__device__ float g_S2[8 * 192 * 192];

// ---------------- helpers ----------------
__device__ __forceinline__ uint32_t smem_u32(const void* p) {
    uint32_t a;
    asm("{ .reg .u64 t; cvta.to.shared.u64 t, %1; cvt.u32.u64 %0, t; }" : "=r"(a) : "l"(p));
    return a;
}
__device__ __forceinline__ uint32_t packbf(float lo, float hi) {
    uint32_t d; asm("cvt.rn.bf16x2.f32 %0, %1, %2;" : "=r"(d) : "f"(hi), "f"(lo)); return d;
}
__device__ __forceinline__ uint32_t bmul2(uint32_t a, uint32_t b) {
    uint32_t d; asm("mul.rn.bf16x2 %0, %1, %2;" : "=r"(d) : "r"(a), "r"(b)); return d;
}
__device__ __forceinline__ void mma16816(float* d, const uint32_t* a, const uint32_t* b,
                                         const float* c) {
    asm volatile(
        "mma.sync.aligned.m16n8k16.row.col.f32.bf16.bf16.f32 "
        "{%0,%1,%2,%3}, {%4,%5,%6,%7}, {%8,%9}, {%10,%11,%12,%13};"
        : "=f"(d[0]), "=f"(d[1]), "=f"(d[2]), "=f"(d[3])
        : "r"(a[0]), "r"(a[1]), "r"(a[2]), "r"(a[3]), "r"(b[0]), "r"(b[1]),
          "f"(c[0]), "f"(c[1]), "f"(c[2]), "f"(c[3]));
}
#define MBAR_INIT(mb, cnt) asm volatile("mbarrier.init.shared.b64 [%0], %1;" :: "r"((uint32_t)(mb)), "r"((uint32_t)(cnt)) : "memory")
#define MBAR_EXPECT_TX(mb, n) asm volatile("mbarrier.arrive.expect_tx.shared.b64 _, [%0], %1;" :: "r"((uint32_t)(mb)), "r"((uint32_t)(n)) : "memory")
#define MBAR_ARRIVE(mb) asm volatile("mbarrier.arrive.release.cta.shared::cta.b64 _, [%0];" :: "r"((uint32_t)(mb)) : "memory")
#define FENCE_ASYNC() asm volatile("fence.proxy.async.shared::cta;" ::: "memory")
#define NBAR(id, cnt) asm volatile("bar.sync %0, %1;" :: "r"(id), "r"(cnt) : "memory")
#define MBAR_WAIT(mb, ph) do { \
    uint32_t _m = (uint32_t)(mb); uint32_t _p = (uint32_t)(ph); uint32_t _d; \
    asm volatile("{\n\t.reg .pred p;\n\tmbarrier.try_wait.parity.acquire.cta.shared::cta.b64 p, [%1], %2;\n\tselp.b32 %0, 1, 0, p;\n\t}" \
        : "=r"(_d) : "r"(_m), "r"(_p) : "memory"); \
    if (!_d) { \
        asm volatile("{\n\t.reg .pred P1;\n\tWL_%=:\n\tmbarrier.try_wait.parity.acquire.cta.shared::cta.b64 P1, [%0], %1, 0x989680;\n\t@P1 bra.uni WD_%=;\n\tbra.uni WL_%=;\n\tWD_%=:\n\t}" \
            :: "r"(_m), "r"(_p) : "memory"); \
    } } while (0)
__device__ __forceinline__ void bulk_g2s(uint32_t dst, const void* src, uint32_t bytes, uint32_t mbar) {
    asm volatile("cp.async.bulk.shared::cta.global.mbarrier::complete_tx::bytes [%0], [%1], %2, [%3];"
        :: "r"(dst), "l"(src), "r"(bytes), "r"(mbar) : "memory");
}

// ---------------- prep: E -> interleaved bf16x2 ----------------
__global__ void kprep_e(const float* __restrict__ E) {
    int idx = blockIdx.x * 256 + threadIdx.x;
    if (idx >= 1536 * EPITCH) return;
    int r = idx / EPITCH, pos = idx % EPITCH;
    int g = pos >> 3, wi = pos & 7, q = wi >> 1, h = wi & 1;
    int kw = g * 8 + q + 4 * h;
    uint32_t v = 0;
    if (kw < 384) {
        float2 e = *reinterpret_cast<const float2*>(E + (size_t)r * 768 + 2 * kw);
        v = packbf(e.x, e.y);
    }
    g_Ebf[idx] = v;
}

// ---------------- prep: weights ----------------
#define WAB_N (12 * 320 * 72)
__global__ void kprep_w(const float* __restrict__ W1, const float* __restrict__ W2) {
    int idx = blockIdx.x * 256 + threadIdx.x;
    if (idx < WAB_N) {
        int c = idx / (320 * 72), rem = idx % (320 * 72);
        int n = rem / 72, kk = rem % 72;
        float v = 0.f;
        if (kk < 64) {
            int kg = c * 64 + kk;
            if (n < 160) { if (n < HH) v = W1[(size_t)kg * HH + n]; }
            else { int h = n - 160; if (h < HH) v = W1[(size_t)(768 + kg) * HH + h]; }
        }
        g_wabT[idx] = __float2bfloat16(v);
    } else if (idx < WAB_N + W1C_WORDS + W2_WORDS) {
        int t = idx - WAB_N;
        bool isW2 = (t >= W1C_WORDS);
        int r = isW2 ? (t - W1C_WORDS) : t;
        int ks = r / PKS, r1 = r % PKS;
        int lane = r1 / 44, r2 = r1 % 44;
        uint32_t v = 0;
        if (r2 < 40) {
            int nh = r2 / 20, r3 = r2 % 20, m = r3 / 4, e = r3 % 4;
            int gq = lane >> 2, qq = lane & 3;
            int nb = nh * 10 + 2 * m + (e >> 1);
            int kwl = ks * 8 + qq + (e & 1) * 4;
            int n = nb * 8 + gq;
            float v0 = 0.f, v1 = 0.f;
            if (n < HH) {
                int k0 = 2 * kwl;
                if (isW2) {
                    if (k0 < HH)     v0 = W2[(size_t)k0 * HH + n];
                    if (k0 + 1 < HH) v1 = W2[(size_t)(k0 + 1) * HH + n];
                } else {
                    v0 = W1[(size_t)(1536 + k0) * HH + n];
                    v1 = W1[(size_t)(1536 + k0 + 1) * HH + n];
                }
            }
            v = packbf(v0, v1);
        }
        if (isW2) g_w2P[r] = v; else g_w1cP[r] = v;
    }
}

// ---------------- k1: seeds GEMM -> g_A,g_B (pitch 152) ----------------
#define K1_E_BYTES (32 * EPITCH * 4)
#define K1_W_BYTES (320 * WABPITCH * 4)
#define K1_BAR_OFF (K1_E_BYTES + 2 * K1_W_BYTES)
#define K1_SMEM    (K1_BAR_OFF + 64)

__global__ __launch_bounds__(256, 1)
void k1_mma(const float* __restrict__ b1) {
    extern __shared__ __align__(128) char smem[];
    uint32_t* sE = (uint32_t*)smem;
    uint32_t* sW[2] = { (uint32_t*)(smem + K1_E_BYTES),
                        (uint32_t*)(smem + K1_E_BYTES + K1_W_BYTES) };
    const uint32_t barE = smem_u32(smem + K1_BAR_OFF);
    const uint32_t barW[2] = { barE + 8, barE + 16 };
    const int tid = threadIdx.x, w = tid >> 5, lane = tid & 31;
    const int gq = lane >> 2, qq = lane & 3;
    const int r0 = blockIdx.x * 32;

    if (tid == 0) {
        MBAR_INIT(barE, 1); MBAR_INIT(barW[0], 1); MBAR_INIT(barW[1], 1);
        FENCE_ASYNC();
        MBAR_EXPECT_TX(barE, K1_E_BYTES);
        bulk_g2s(smem_u32(sE), g_Ebf + (size_t)r0 * EPITCH, K1_E_BYTES, barE);
        MBAR_EXPECT_TX(barW[0], K1_W_BYTES);
        bulk_g2s(smem_u32(sW[0]), g_wabT, K1_W_BYTES, barW[0]);
        MBAR_EXPECT_TX(barW[1], K1_W_BYTES);
        bulk_g2s(smem_u32(sW[1]), g_wabT + (size_t)320 * 72, K1_W_BYTES, barW[1]);
    }
    __syncthreads();
    MBAR_WAIT(barE, 0);

    float acc[2][5][4];
#pragma unroll
    for (int t = 0; t < 2; t++)
#pragma unroll
        for (int l = 0; l < 5; l++)
#pragma unroll
            for (int u = 0; u < 4; u++) acc[t][l][u] = 0.f;

    const uint32_t* e0p = sE + (size_t)gq * EPITCH;
    const uint32_t* e1p = e0p + 8 * EPITCH;
    const uint32_t* e2p = e0p + 16 * EPITCH;
    const uint32_t* e3p = e0p + 24 * EPITCH;

    for (int c = 0; c < 12; c++) {
        MBAR_WAIT(barW[c & 1], (c >> 1) & 1);
        const uint32_t* Wb = sW[c & 1];
#pragma unroll
        for (int ks = 0; ks < 4; ks++) {
            int kb = c * 32 + ks * 8 + 2 * qq;
            uint2 e0 = *(const uint2*)(e0p + kb);
            uint2 e1 = *(const uint2*)(e1p + kb);
            uint2 e2 = *(const uint2*)(e2p + kb);
            uint2 e3 = *(const uint2*)(e3p + kb);
            uint32_t a0[4] = { e0.x, e1.x, e0.y, e1.y };
            uint32_t a1[4] = { e2.x, e3.x, e2.y, e3.y };
#pragma unroll
            for (int l = 0; l < 5; l++) {
                int nrow = (w * 5 + l) * 8 + gq;
                uint32_t b[2] = { Wb[nrow * WABPITCH + ks * 8 + qq],
                                  Wb[nrow * WABPITCH + ks * 8 + qq + 4] };
                mma16816(acc[0][l], a0, b, acc[0][l]);
                mma16816(acc[1][l], a1, b, acc[1][l]);
            }
        }
        __syncthreads();
        if (tid == 0 && c + 2 < 12) {
            MBAR_EXPECT_TX(barW[c & 1], K1_W_BYTES);
            bulk_g2s(smem_u32(sW[c & 1]), g_wabT + (size_t)(c + 2) * 320 * 72,
                     K1_W_BYTES, barW[c & 1]);
        }
    }

#pragma unroll
    for (int t = 0; t < 2; t++)
#pragma unroll
        for (int l = 0; l < 5; l++) {
            int n0 = (w * 5 + l) * 8 + 2 * qq;
            int ra = r0 + 16 * t + gq, rb = ra + 8;
#pragma unroll
            for (int u = 0; u < 4; u++) {
                int row = (u < 2) ? ra : rb;
                int n = n0 + (u & 1);
                float v = acc[t][l][u];
                if (n < 160) { if (n < HH) g_A[(size_t)row * APITCH + n] = v + __ldg(b1 + n); }
                else { int h = n - 160; if (h < HH) g_B[(size_t)row * APITCH + h] = v; }
            }
        }
}

// ---------------- k2: persistent (static stride), 2 CTAs/SM, 4-deep W ring ----------------
// grid 296; block handles tiles cur = bid, bid+296, ... All pipeline phases are
// derived from the running slot counter gs (registers only — no indexed arrays).
#define K2_EI_OFF   0                                  // 12*392*4 = 18816
#define K2_EJ_OFF   18816                              // 8*392*4  = 12544
#define K2_W_OFF    31360                              // 4 x 11264 = 45056
#define K2_H1_OFF   76416                              // 96*88*4 = 33792
#define K2_BW_OFF   110208                             // b2|W3: 1216
#define K2_BAR_OFF  111424
#define K2_SMEM     (K2_BAR_OFF + 128)                 // 111552

__device__ __forceinline__ void k2_decode(int tt, int& bz, int& ti, int& tj) {
    bz = tt / 208;
    int x = tt - bz * 208;
    const int cumt[16] = {0,2,5,10,16,24,33,44,56,70,85,102,120,140,161,184};
    int t = 0;
#pragma unroll
    for (int k = 1; k < 16; k++)
        if (cumt[k] <= x) t = k;
    ti = t; tj = x - cumt[t];
}

__global__ __launch_bounds__(192, 2)
void k2_mma(const float* __restrict__ b2,
            const float* __restrict__ W3) {
    extern __shared__ __align__(128) char smem[];
    uint32_t* sEi = (uint32_t*)(smem + K2_EI_OFF);
    uint32_t* sEj = (uint32_t*)(smem + K2_EJ_OFF);
    uint32_t* sWr = (uint32_t*)(smem + K2_W_OFF);      // ring: 4 x SLAB_W
    uint32_t* sH1 = (uint32_t*)(smem + K2_H1_OFF);
    float*    sB2 = (float*)(smem + K2_BW_OFF);
    float*    sW3 = sB2 + 152;
    const uint32_t barE  = smem_u32(smem + K2_BAR_OFF);
    const uint32_t barW0 = barE + 8;    // barW[b] = barW0 + 8b
    const uint32_t barC0 = barE + 40;   // barC[b] = barC0 + 8b
    const uint32_t barEF = barE + 72;
    const int tid = threadIdx.x, w = tid >> 5, lane = tid & 31;
    const int mh = w >> 1, nh = w & 1;
    const int gq = lane >> 2, qq = lane & 3;

    const int nMyTiles = (NTILES - 1 - (int)blockIdx.x) / K2_GRID + 1;
    const int totalSlabs = nMyTiles * SLOTS_PER_TILE;

    if (tid == 0) {
        MBAR_INIT(barE, 1); MBAR_INIT(barEF, 6);
#pragma unroll
        for (int b = 0; b < 4; b++) { MBAR_INIT(barW0 + 8 * b, 1); MBAR_INIT(barC0 + 8 * b, 6); }
        FENCE_ASYNC();
        int bz, ti, tj; k2_decode(blockIdx.x, bz, ti, tj);
        MBAR_EXPECT_TX(barE, (12 + 8) * EPITCH * 4);
        bulk_g2s(smem_u32(sEi), g_Ebf + ((size_t)bz * 192 + ti * 12) * EPITCH, 12 * EPITCH * 4, barE);
        bulk_g2s(smem_u32(sEj), g_Ebf + ((size_t)bz * 192 + tj * 8) * EPITCH, 8 * EPITCH * 4, barE);
#pragma unroll
        for (int f = 0; f < 4; f++) {
            MBAR_EXPECT_TX(barW0 + 8 * f, SLAB_W * 4);
            bulk_g2s(smem_u32(sWr + f * SLAB_W), g_w1cP + (size_t)f * SLAB_W,
                     SLAB_W * 4, barW0 + 8 * f);
        }
    }
    for (int idx = tid; idx < 304; idx += 192) {
        if (idx < 152) sB2[idx] = (idx < HH) ? b2[idx] : 0.f;
        else { int h = idx - 152; sW3[h] = (h < HH) ? W3[h] : 0.f; }
    }
    for (int idx = tid; idx < 96 * 4; idx += 192)
        sH1[(idx >> 2) * H1PITCH + 76 + (idx & 3)] = 0;
    __syncthreads();

    const uint32_t* eI0 = sEi + (size_t)(4 * mh + 0) * EPITCH;
    const uint32_t* eI1 = sEi + (size_t)(4 * mh + 1) * EPITCH;
    const uint32_t* eI2 = sEi + (size_t)(4 * mh + 2) * EPITCH;
    const uint32_t* eI3 = sEi + (size_t)(4 * mh + 3) * EPITCH;
    const uint32_t* eJp = sEj + (size_t)gq * EPITCH;
    const uint32_t* h0p = sH1 + (size_t)(32 * mh + gq) * H1PITCH;
    const uint32_t* h1p = h0p + 8 * H1PITCH;
    const uint32_t* h2p = h0p + 16 * H1PITCH;
    const uint32_t* h3p = h0p + 24 * H1PITCH;
    const int bw_off = lane * 44 + nh * 20;
    const bool full_n = (nh == 0);   // nh==1 skips all-zero n-block 19

#define MMA_NBLOCKS(ACC, a0, a1, bp) do { \
        _Pragma("unroll") \
        for (int m = 0; m < 4; m++) { \
            uint4 bb = *(const uint4*)((bp) + m * 4); \
            uint32_t b0[2] = { bb.x, bb.y }; \
            uint32_t b1r[2] = { bb.z, bb.w }; \
            mma16816(ACC[0][2 * m],     a0, b0,  ACC[0][2 * m]); \
            mma16816(ACC[1][2 * m],     a1, b0,  ACC[1][2 * m]); \
            mma16816(ACC[0][2 * m + 1], a0, b1r, ACC[0][2 * m + 1]); \
            mma16816(ACC[1][2 * m + 1], a1, b1r, ACC[1][2 * m + 1]); \
        } \
        { \
            uint4 bb = *(const uint4*)((bp) + 16); \
            uint32_t b0[2] = { bb.x, bb.y }; \
            mma16816(ACC[0][8], a0, b0, ACC[0][8]); \
            mma16816(ACC[1][8], a1, b0, ACC[1][8]); \
            if (full_n) { \
                uint32_t b1r[2] = { bb.z, bb.w }; \
                mma16816(ACC[0][9], a0, b1r, ACC[0][9]); \
                mma16816(ACC[1][9], a1, b1r, ACC[1][9]); \
            } \
        } \
    } while (0)

    // per-slab pipeline step (consume + issuer refill), all phases from gs
#define SLAB_EPILOG() do { \
        __syncwarp(); \
        if (lane == 0) MBAR_ARRIVE(barC0 + 8 * (gs & 3)); \
        if (w == 0 && lane == 0) { \
            MBAR_WAIT(barC0 + 8 * (gs & 3), (gs >> 2) & 1); \
            int tgt = gs + 4; \
            if (tgt < totalSlabs) { \
                int ns = tgt % SLOTS_PER_TILE; \
                const uint32_t* src = (ns < 24) ? g_w1cP + (size_t)ns * SLAB_W \
                                                : g_w2P + (size_t)(ns - 24) * SLAB_W; \
                MBAR_EXPECT_TX(barW0 + 8 * (gs & 3), SLAB_W * 4); \
                bulk_g2s(smem_u32(sWr + (gs & 3) * SLAB_W), src, SLAB_W * 4, \
                         barW0 + 8 * (gs & 3)); \
            } \
        } \
    } while (0)

    int gs = 0;
    int tileIdx = 0;
    for (int cur = blockIdx.x; cur < NTILES; cur += K2_GRID, tileIdx++) {
        int bz, ti, tj; k2_decode(cur, bz, ti, tj);
        MBAR_WAIT(barE, tileIdx & 1);

        float acc[2][10][4];
#pragma unroll
        for (int t = 0; t < 2; t++)
#pragma unroll
            for (int l = 0; l < 10; l++)
#pragma unroll
                for (int u = 0; u < 4; u++) acc[t][l][u] = 0.f;

        // ---- layer 1: 24 slabs ----
        for (int f = 0; f < 24; f++, gs++) {
            MBAR_WAIT(barW0 + 8 * (gs & 3), (gs >> 2) & 1);
            const uint32_t* Wb = sWr + (gs & 3) * SLAB_W;
#pragma unroll
            for (int ks = 0; ks < 2; ks++) {
                int kb = f * 16 + ks * 8 + 2 * qq;
                uint2 ej = *(const uint2*)(eJp + kb);
                uint2 e0 = *(const uint2*)(eI0 + kb);
                uint2 e1 = *(const uint2*)(eI1 + kb);
                uint2 e2 = *(const uint2*)(eI2 + kb);
                uint2 e3 = *(const uint2*)(eI3 + kb);
                uint32_t a0[4] = { bmul2(e0.x, ej.x), bmul2(e1.x, ej.x),
                                   bmul2(e0.y, ej.y), bmul2(e1.y, ej.y) };
                uint32_t a1[4] = { bmul2(e2.x, ej.x), bmul2(e3.x, ej.x),
                                   bmul2(e2.y, ej.y), bmul2(e3.y, ej.y) };
                const uint32_t* bp = Wb + ks * PKS + bw_off;
                MMA_NBLOCKS(acc, a0, a1, bp);
            }
            if (f == 23) {
                __syncwarp();
                if (lane == 0) MBAR_ARRIVE(barEF);   // this warp done reading E
            }
            SLAB_EPILOG();
            if (f == 23 && w == 0 && lane == 0) {
                // overwrite E buffers with next tile once all warps are done with them
                MBAR_WAIT(barEF, tileIdx & 1);
                int nxt = cur + K2_GRID;
                if (nxt < NTILES) {
                    int nbz, nti, ntj; k2_decode(nxt, nbz, nti, ntj);
                    MBAR_EXPECT_TX(barE, (12 + 8) * EPITCH * 4);
                    bulk_g2s(smem_u32(sEi), g_Ebf + ((size_t)nbz * 192 + nti * 12) * EPITCH,
                             12 * EPITCH * 4, barE);
                    bulk_g2s(smem_u32(sEj), g_Ebf + ((size_t)nbz * 192 + ntj * 8) * EPITCH,
                             8 * EPITCH * 4, barE);
                }
            }
        }

        // ---- epilogue 1: + seeds (L2 gmem), ReLU, bf16 -> sH1 ----
        {
            const float* Bj = g_B + ((size_t)bz * 192 + tj * 8 + gq) * APITCH;
#pragma unroll
            for (int t = 0; t < 2; t++) {
                const float* A0 = g_A + ((size_t)bz * 192 + ti * 12 + 4 * mh + 2 * t) * APITCH;
                const float* A1 = A0 + APITCH;
#pragma unroll
                for (int l = 0; l < 10; l++) {
                    if (l == 9 && !full_n) break;
                    int nbg = nh * 10 + l;
                    int h0 = nbg * 8 + 2 * qq;
                    float v0 = 0.f, v1 = 0.f, v2 = 0.f, v3 = 0.f;
                    if (h0 < HH) {
                        float2 a0v = *(const float2*)(A0 + h0);
                        float2 a1v = *(const float2*)(A1 + h0);
                        float2 bjv = *(const float2*)(Bj + h0);
                        v0 = fmaxf(acc[t][l][0] + a0v.x + bjv.x, 0.f);
                        v1 = fmaxf(acc[t][l][1] + a0v.y + bjv.y, 0.f);
                        v2 = fmaxf(acc[t][l][2] + a1v.x + bjv.x, 0.f);
                        v3 = fmaxf(acc[t][l][3] + a1v.y + bjv.y, 0.f);
                    }
                    int kw = nbg * 4 + qq;
                    int ilvw = ((kw >> 3) << 3) + 2 * (kw & 3) + ((kw >> 2) & 1);
                    sH1[(32 * mh + 16 * t + gq) * H1PITCH + ilvw]     = packbf(v0, v1);
                    sH1[(32 * mh + 16 * t + 8 + gq) * H1PITCH + ilvw] = packbf(v2, v3);
                }
            }
        }
        NBAR(1 + mh, 64);      // nh-pair exchange of h1 halves

        // ---- layer 2: 5 slabs ----
        float ac2[2][10][4];
#pragma unroll
        for (int t = 0; t < 2; t++)
#pragma unroll
            for (int l = 0; l < 10; l++)
#pragma unroll
                for (int u = 0; u < 4; u++) ac2[t][l][u] = 0.f;

        for (int f2 = 0; f2 < 5; f2++, gs++) {
            MBAR_WAIT(barW0 + 8 * (gs & 3), (gs >> 2) & 1);
            const uint32_t* Wb = sWr + (gs & 3) * SLAB_W;
#pragma unroll
            for (int ks2 = 0; ks2 < 2; ks2++) {
                int kb = f2 * 16 + ks2 * 8 + 2 * qq;
                uint2 x0 = *(const uint2*)(h0p + kb);
                uint2 x1 = *(const uint2*)(h1p + kb);
                uint2 x2 = *(const uint2*)(h2p + kb);
                uint2 x3 = *(const uint2*)(h3p + kb);
                uint32_t a0[4] = { x0.x, x1.x, x0.y, x1.y };
                uint32_t a1[4] = { x2.x, x3.x, x2.y, x3.y };
                const uint32_t* bp = Wb + ks2 * PKS + bw_off;
                MMA_NBLOCKS(ac2, a0, a1, bp);
            }
            SLAB_EPILOG();
        }

        // ---- epilogue 2: +b2, ReLU, dot W3; partials to g_S / g_S2 ----
        float sp[2][2] = { {0.f, 0.f}, {0.f, 0.f} };
#pragma unroll
        for (int t = 0; t < 2; t++)
#pragma unroll
            for (int l = 0; l < 10; l++) {
                if (l == 9 && !full_n) break;
                int h0 = (nh * 10 + l) * 8 + 2 * qq;
                if (h0 < HH) {
                    float2 bv = *(const float2*)(sB2 + h0);
                    float2 wv = *(const float2*)(sW3 + h0);
                    sp[t][0] += fmaxf(ac2[t][l][0] + bv.x, 0.f) * wv.x
                              + fmaxf(ac2[t][l][1] + bv.y, 0.f) * wv.y;
                    sp[t][1] += fmaxf(ac2[t][l][2] + bv.x, 0.f) * wv.x
                              + fmaxf(ac2[t][l][3] + bv.y, 0.f) * wv.y;
                }
            }
#pragma unroll
        for (int t = 0; t < 2; t++)
#pragma unroll
            for (int s = 0; s < 2; s++) {
                sp[t][s] += __shfl_xor_sync(0xffffffffu, sp[t][s], 1);
                sp[t][s] += __shfl_xor_sync(0xffffffffu, sp[t][s], 2);
            }
        if (qq == 0) {
            float* dst = full_n ? g_S2 : g_S;
#pragma unroll
            for (int t = 0; t < 2; t++)
#pragma unroll
                for (int s = 0; s < 2; s++) {
                    int r = 32 * mh + 16 * t + 8 * s + gq;
                    int ip = ti * 12 + (r >> 3), jp = tj * 8 + (r & 7);
                    if (jp < ip)
                        dst[((size_t)bz * 192 + ip) * 192 + jp] = sp[t][s];
                }
        }

        __syncthreads();   // sH1 reuse + E-buffer phase safety across tiles
    }
}

// ---------------- k3: tril softmax (sums the two partial-score arrays) ----------------
__global__ void k3_softmax(float* __restrict__ out, const float* __restrict__ b3) {
    const int i = blockIdx.x, b = blockIdx.y, j = threadIdx.x;
    const float b3v = __ldg(b3);
    float val;
    if (j < i) {
        size_t idx = ((size_t)b * 192 + i) * 192 + j;
        val = g_S[idx] + g_S2[idx] + b3v;
    } else if (j == i) val = 0.f;
    else               val = -1e30f;

    __shared__ float red[6];
    float m = val;
#pragma unroll
    for (int o = 16; o; o >>= 1) m = fmaxf(m, __shfl_xor_sync(0xffffffffu, m, o));
    if ((j & 31) == 0) red[j >> 5] = m;
    __syncthreads();
    float M = fmaxf(fmaxf(fmaxf(red[0], red[1]), fmaxf(red[2], red[3])), fmaxf(red[4], red[5]));
    __syncthreads();
    float e = (j <= i) ? expf(val - M) : 0.f;
    float s = e;
#pragma unroll
    for (int o = 16; o; o >>= 1) s += __shfl_xor_sync(0xffffffffu, s, o);
    if ((j & 31) == 0) red[j >> 5] = s;
    __syncthreads();
    float S = red[0] + red[1] + red[2] + red[3] + red[4] + red[5];
    out[((size_t)b * 192 + i) * 192 + j] = (j <= i) ? (e / S) : -1000.0f;
}

// ---------------------------------------------------------------------------
extern "C" void kernel_launch(void* const* d_in, const int* in_sizes, int n_in,
                              void* d_out, int out_size) {
    const float* E  = (const float*)d_in[0];
    const float* W1 = (const float*)d_in[1];
    const float* b1 = (const float*)d_in[2];
    const float* W2 = (const float*)d_in[3];
    const float* b2 = (const float*)d_in[4];
    const float* W3 = (const float*)d_in[5];
    const float* b3 = (const float*)d_in[6];
    float* out = (float*)d_out;

    cudaFuncSetAttribute(k1_mma, cudaFuncAttributeMaxDynamicSharedMemorySize, K1_SMEM);
    cudaFuncSetAttribute(k2_mma, cudaFuncAttributeMaxDynamicSharedMemorySize, K2_SMEM);

    kprep_e<<<(1536 * EPITCH + 255) / 256, 256>>>(E);
    kprep_w<<<(WAB_N + W1C_WORDS + W2_WORDS + 255) / 256, 256>>>(W1, W2);
    k1_mma<<<48, 256, K1_SMEM>>>(b1);
    k2_mma<<<K2_GRID, 192, K2_SMEM>>>(b2, W3);
    k3_softmax<<<dim3(192, 8), 192>>>(out, b3);
}

// round 14
// speedup vs baseline: 1.1937x; 1.0322x over previous
#include <cuda_runtime.h>
#include <cuda_bf16.h>
#include <cstdint>

#define HH 150
#define APITCH 152          // g_A/g_B row pitch (floats)

#define EPITCH 392          // E row pitch (u32) — k1, k16-interleaved
#define EP2W 400            // E row pitch (u32) — k2, 2-ks-interleaved (%32==16)
#define H1PITCH 88          // h1 row pitch in u32 words
#define WABPITCH 36         // k1 weight row pitch (u32 words)

// Packed-fragment W blob geometry: per k16-step: 32 lanes * 44 words
#define PKS 1408
#define W1C_WORDS (48 * PKS)
#define W2_WORDS  (10 * PKS)
#define SLAB_W (2 * PKS)    // 2 ks per fetch slab (11264 B)
#define NSLOT 29            // 24 W1c + 5 W2

// ---------------- device scratch ----------------
__device__ __align__(16) uint32_t      g_Ebf[1536 * EPITCH];   // k1 E
__device__ __align__(16) uint32_t      g_Ef2[1536 * EP2W];     // k2 E (2-ks groups)
__device__ __align__(16) __nv_bfloat16 g_wabT[12 * 320 * 72];
__device__ __align__(16) uint32_t      g_w1cP[W1C_WORDS];
__device__ __align__(16) uint32_t      g_w2P[W2_WORDS];
__device__ __align__(16) float g_A[1536 * APITCH];
__device__ __align__(16) float g_B[1536 * APITCH];
__device__ float g_S[8 * 192 * 192];
__device__ float g_S2[8 * 192 * 192];

// ---------------- helpers ----------------
__device__ __forceinline__ uint32_t smem_u32(const void* p) {
    uint32_t a;
    asm("{ .reg .u64 t; cvta.to.shared.u64 t, %1; cvt.u32.u64 %0, t; }" : "=r"(a) : "l"(p));
    return a;
}
__device__ __forceinline__ uint32_t packbf(float lo, float hi) {
    uint32_t d; asm("cvt.rn.bf16x2.f32 %0, %1, %2;" : "=r"(d) : "f"(hi), "f"(lo)); return d;
}
__device__ __forceinline__ uint32_t bmul2(uint32_t a, uint32_t b) {
    uint32_t d; asm("mul.rn.bf16x2 %0, %1, %2;" : "=r"(d) : "r"(a), "r"(b)); return d;
}
__device__ __forceinline__ void mma16816(float* d, const uint32_t* a, const uint32_t* b,
                                         const float* c) {
    asm volatile(
        "mma.sync.aligned.m16n8k16.row.col.f32.bf16.bf16.f32 "
        "{%0,%1,%2,%3}, {%4,%5,%6,%7}, {%8,%9}, {%10,%11,%12,%13};"
        : "=f"(d[0]), "=f"(d[1]), "=f"(d[2]), "=f"(d[3])
        : "r"(a[0]), "r"(a[1]), "r"(a[2]), "r"(a[3]), "r"(b[0]), "r"(b[1]),
          "f"(c[0]), "f"(c[1]), "f"(c[2]), "f"(c[3]));
}
#define MBAR_INIT(mb, cnt) asm volatile("mbarrier.init.shared.b64 [%0], %1;" :: "r"((uint32_t)(mb)), "r"((uint32_t)(cnt)) : "memory")
#define MBAR_EXPECT_TX(mb, n) asm volatile("mbarrier.arrive.expect_tx.shared.b64 _, [%0], %1;" :: "r"((uint32_t)(mb)), "r"((uint32_t)(n)) : "memory")
#define MBAR_ARRIVE(mb) asm volatile("mbarrier.arrive.release.cta.shared::cta.b64 _, [%0];" :: "r"((uint32_t)(mb)) : "memory")
#define FENCE_ASYNC() asm volatile("fence.proxy.async.shared::cta;" ::: "memory")
#define NBAR(id, cnt) asm volatile("bar.sync %0, %1;" :: "r"(id), "r"(cnt) : "memory")
#define MBAR_WAIT(mb, ph) do { \
    uint32_t _m = (uint32_t)(mb); uint32_t _p = (uint32_t)(ph); uint32_t _d; \
    asm volatile("{\n\t.reg .pred p;\n\tmbarrier.try_wait.parity.acquire.cta.shared::cta.b64 p, [%1], %2;\n\tselp.b32 %0, 1, 0, p;\n\t}" \
        : "=r"(_d) : "r"(_m), "r"(_p) : "memory"); \
    if (!_d) { \
        asm volatile("{\n\t.reg .pred P1;\n\tWL_%=:\n\tmbarrier.try_wait.parity.acquire.cta.shared::cta.b64 P1, [%0], %1, 0x989680;\n\t@P1 bra.uni WD_%=;\n\tbra.uni WL_%=;\n\tWD_%=:\n\t}" \
            :: "r"(_m), "r"(_p) : "memory"); \
    } } while (0)
__device__ __forceinline__ void bulk_g2s(uint32_t dst, const void* src, uint32_t bytes, uint32_t mbar) {
    asm volatile("cp.async.bulk.shared::cta.global.mbarrier::complete_tx::bytes [%0], [%1], %2, [%3];"
        :: "r"(dst), "l"(src), "r"(bytes), "r"(mbar) : "memory");
}

// ---------------- merged prep: E (both layouts) + weights ----------------
#define PE_N  (1536 * EPITCH)
#define PE2_N (1536 * EP2W)
#define WAB_N (12 * 320 * 72)
__global__ void kprep(const float* __restrict__ E,
                      const float* __restrict__ W1, const float* __restrict__ W2) {
    int idx = blockIdx.x * 256 + threadIdx.x;
    if (idx < PE_N) {
        // k1 E: k16-interleaved, word p in 8-group encodes (q,h): p=2q+h, kw=g*8+q+4h
        int r = idx / EPITCH, pos = idx % EPITCH;
        int g = pos >> 3, wi = pos & 7, q = wi >> 1, h = wi & 1;
        int kw = g * 8 + q + 4 * h;
        uint32_t v = 0;
        if (kw < 384) {
            float2 e = *reinterpret_cast<const float2*>(E + (size_t)r * 768 + 2 * kw);
            v = packbf(e.x, e.y);
        }
        g_Ebf[idx] = v;
    } else if (idx < PE_N + PE2_N) {
        // k2 E: 2-ks groups of 16 words; thread qq's 4 words contiguous at 4*qq:
        // [ks0h0, ks0h1, ks1h0, ks1h1]; kw = g2*16 + ks*8 + qq + 4h
        int t = idx - PE_N;
        int r = t / EP2W, pos = t % EP2W;
        int g2 = pos >> 4, w16 = pos & 15;
        int qq = w16 >> 2, c = w16 & 3;
        int ks = c >> 1, h = c & 1;
        int kw = g2 * 16 + ks * 8 + qq + 4 * h;
        uint32_t v = 0;
        if (kw < 384) {
            float2 e = *reinterpret_cast<const float2*>(E + (size_t)r * 768 + 2 * kw);
            v = packbf(e.x, e.y);
        }
        g_Ef2[t] = v;
    } else if (idx < PE_N + PE2_N + WAB_N) {
        int t = idx - PE_N - PE2_N;
        int c = t / (320 * 72), rem = t % (320 * 72);
        int n = rem / 72, kk = rem % 72;
        float v = 0.f;
        if (kk < 64) {
            int kg = c * 64 + kk;
            if (n < 160) { if (n < HH) v = W1[(size_t)kg * HH + n]; }
            else { int h = n - 160; if (h < HH) v = W1[(size_t)(768 + kg) * HH + h]; }
        }
        g_wabT[t] = __float2bfloat16(v);
    } else if (idx < PE_N + PE2_N + WAB_N + W1C_WORDS + W2_WORDS) {
        int t = idx - PE_N - PE2_N - WAB_N;
        bool isW2 = (t >= W1C_WORDS);
        int r = isW2 ? (t - W1C_WORDS) : t;
        int ks = r / PKS, r1 = r % PKS;
        int lane = r1 / 44, r2 = r1 % 44;
        uint32_t v = 0;
        if (r2 < 40) {
            int nh = r2 / 20, r3 = r2 % 20, m = r3 / 4, e = r3 % 4;
            int gq = lane >> 2, qq = lane & 3;
            int nb = nh * 10 + 2 * m + (e >> 1);
            int kwl = ks * 8 + qq + (e & 1) * 4;
            int n = nb * 8 + gq;
            float v0 = 0.f, v1 = 0.f;
            if (n < HH) {
                int k0 = 2 * kwl;
                if (isW2) {
                    if (k0 < HH)     v0 = W2[(size_t)k0 * HH + n];
                    if (k0 + 1 < HH) v1 = W2[(size_t)(k0 + 1) * HH + n];
                } else {
                    v0 = W1[(size_t)(1536 + k0) * HH + n];
                    v1 = W1[(size_t)(1536 + k0 + 1) * HH + n];
                }
            }
            v = packbf(v0, v1);
        }
        if (isW2) g_w2P[r] = v; else g_w1cP[r] = v;
    }
}

// ---------------- k1: seeds GEMM -> g_A,g_B (pitch 152) ----------------
#define K1_E_BYTES (32 * EPITCH * 4)
#define K1_W_BYTES (320 * WABPITCH * 4)
#define K1_BAR_OFF (K1_E_BYTES + 2 * K1_W_BYTES)
#define K1_SMEM    (K1_BAR_OFF + 64)

__global__ __launch_bounds__(256, 1)
void k1_mma(const float* __restrict__ b1) {
    extern __shared__ __align__(128) char smem[];
    uint32_t* sE = (uint32_t*)smem;
    uint32_t* sW[2] = { (uint32_t*)(smem + K1_E_BYTES),
                        (uint32_t*)(smem + K1_E_BYTES + K1_W_BYTES) };
    const uint32_t barE = smem_u32(smem + K1_BAR_OFF);
    const uint32_t barW[2] = { barE + 8, barE + 16 };
    const int tid = threadIdx.x, w = tid >> 5, lane = tid & 31;
    const int gq = lane >> 2, qq = lane & 3;
    const int r0 = blockIdx.x * 32;

    if (tid == 0) {
        MBAR_INIT(barE, 1); MBAR_INIT(barW[0], 1); MBAR_INIT(barW[1], 1);
        FENCE_ASYNC();
        MBAR_EXPECT_TX(barE, K1_E_BYTES);
        bulk_g2s(smem_u32(sE), g_Ebf + (size_t)r0 * EPITCH, K1_E_BYTES, barE);
        MBAR_EXPECT_TX(barW[0], K1_W_BYTES);
        bulk_g2s(smem_u32(sW[0]), g_wabT, K1_W_BYTES, barW[0]);
        MBAR_EXPECT_TX(barW[1], K1_W_BYTES);
        bulk_g2s(smem_u32(sW[1]), g_wabT + (size_t)320 * 72, K1_W_BYTES, barW[1]);
    }
    __syncthreads();
    MBAR_WAIT(barE, 0);

    float acc[2][5][4];
#pragma unroll
    for (int t = 0; t < 2; t++)
#pragma unroll
        for (int l = 0; l < 5; l++)
#pragma unroll
            for (int u = 0; u < 4; u++) acc[t][l][u] = 0.f;

    const uint32_t* e0p = sE + (size_t)gq * EPITCH;
    const uint32_t* e1p = e0p + 8 * EPITCH;
    const uint32_t* e2p = e0p + 16 * EPITCH;
    const uint32_t* e3p = e0p + 24 * EPITCH;

    for (int c = 0; c < 12; c++) {
        MBAR_WAIT(barW[c & 1], (c >> 1) & 1);
        const uint32_t* Wb = sW[c & 1];
#pragma unroll
        for (int ks = 0; ks < 4; ks++) {
            int kb = c * 32 + ks * 8 + 2 * qq;
            uint2 e0 = *(const uint2*)(e0p + kb);
            uint2 e1 = *(const uint2*)(e1p + kb);
            uint2 e2 = *(const uint2*)(e2p + kb);
            uint2 e3 = *(const uint2*)(e3p + kb);
            uint32_t a0[4] = { e0.x, e1.x, e0.y, e1.y };
            uint32_t a1[4] = { e2.x, e3.x, e2.y, e3.y };
#pragma unroll
            for (int l = 0; l < 5; l++) {
                int nrow = (w * 5 + l) * 8 + gq;
                uint32_t b[2] = { Wb[nrow * WABPITCH + ks * 8 + qq],
                                  Wb[nrow * WABPITCH + ks * 8 + qq + 4] };
                mma16816(acc[0][l], a0, b, acc[0][l]);
                mma16816(acc[1][l], a1, b, acc[1][l]);
            }
        }
        __syncthreads();
        if (tid == 0 && c + 2 < 12) {
            MBAR_EXPECT_TX(barW[c & 1], K1_W_BYTES);
            bulk_g2s(smem_u32(sW[c & 1]), g_wabT + (size_t)(c + 2) * 320 * 72,
                     K1_W_BYTES, barW[c & 1]);
        }
    }

#pragma unroll
    for (int t = 0; t < 2; t++)
#pragma unroll
        for (int l = 0; l < 5; l++) {
            int n0 = (w * 5 + l) * 8 + 2 * qq;
            int ra = r0 + 16 * t + gq, rb = ra + 8;
#pragma unroll
            for (int u = 0; u < 4; u++) {
                int row = (u < 2) ? ra : rb;
                int n = n0 + (u & 1);
                float v = acc[t][l][u];
                if (n < 160) { if (n < HH) g_A[(size_t)row * APITCH + n] = v + __ldg(b1 + n); }
                else { int h = n - 160; if (h < HH) g_B[(size_t)row * APITCH + h] = v; }
            }
        }
}

// ---------------- k2: fused pair MLP, 2 CTAs/SM, 4-deep W ring, wide E loads ----------------
// Compact grid (208, 8). 192 thr = 6 warps: mh=w>>1 (m32), nh=w&1 (n80 half). Tile 12x8.
#define K2_EI_OFF   0                                  // 12*400*4 = 19200
#define K2_EJ_OFF   19200                              // 8*400*4  = 12800
#define K2_W_OFF    32000                              // 4 x 11264 = 45056
#define K2_H1_OFF   77056                              // 96*88*4 = 33792
#define K2_BW_OFF   110848                             // b2|W3: 1216
#define K2_BAR_OFF  112064
#define K2_SMEM     (K2_BAR_OFF + 128)                 // 112192

__global__ __launch_bounds__(192, 2)
void k2_mma(const float* __restrict__ b2,
            const float* __restrict__ W3) {
    const int bz = blockIdx.y;
    const int x = blockIdx.x;
    const int cumt[16] = {0,2,5,10,16,24,33,44,56,70,85,102,120,140,161,184};
    int ti = 0;
#pragma unroll
    for (int t = 1; t < 16; t++)
        if (cumt[t] <= x) ti = t;
    const int tj = x - cumt[ti];

    extern __shared__ __align__(128) char smem[];
    uint32_t* sEi = (uint32_t*)(smem + K2_EI_OFF);
    uint32_t* sEj = (uint32_t*)(smem + K2_EJ_OFF);
    uint32_t* sWr = (uint32_t*)(smem + K2_W_OFF);      // ring: 4 x SLAB_W
    uint32_t* sH1 = (uint32_t*)(smem + K2_H1_OFF);
    float*    sB2 = (float*)(smem + K2_BW_OFF);
    float*    sW3 = sB2 + 152;
    const uint32_t barE = smem_u32(smem + K2_BAR_OFF);
    const uint32_t barW0 = barE + 8;    // barW[b] = barW0 + 8b
    const uint32_t barC0 = barE + 40;   // barC[b] = barC0 + 8b
    const int tid = threadIdx.x, w = tid >> 5, lane = tid & 31;
    const int mh = w >> 1, nh = w & 1;
    const int gq = lane >> 2, qq = lane & 3;

    if (tid == 0) {
        MBAR_INIT(barE, 1);
#pragma unroll
        for (int b = 0; b < 4; b++) { MBAR_INIT(barW0 + 8 * b, 1); MBAR_INIT(barC0 + 8 * b, 6); }
        FENCE_ASYNC();
        MBAR_EXPECT_TX(barE, (12 + 8) * EP2W * 4);
        bulk_g2s(smem_u32(sEi), g_Ef2 + ((size_t)bz * 192 + ti * 12) * EP2W, 12 * EP2W * 4, barE);
        bulk_g2s(smem_u32(sEj), g_Ef2 + ((size_t)bz * 192 + tj * 8) * EP2W, 8 * EP2W * 4, barE);
#pragma unroll
        for (int f = 0; f < 4; f++) {
            MBAR_EXPECT_TX(barW0 + 8 * f, SLAB_W * 4);
            bulk_g2s(smem_u32(sWr + f * SLAB_W), g_w1cP + (size_t)f * SLAB_W, SLAB_W * 4, barW0 + 8 * f);
        }
    }
    // stage b2/W3; zero sH1 pad words kw 76..79 (read by L2 ks9 against zero weights)
    for (int idx = tid; idx < 304; idx += 192) {
        if (idx < 152) sB2[idx] = (idx < HH) ? b2[idx] : 0.f;
        else { int h = idx - 152; sW3[h] = (h < HH) ? W3[h] : 0.f; }
    }
    for (int idx = tid; idx < 96 * 4; idx += 192)
        sH1[(idx >> 2) * H1PITCH + 76 + (idx & 3)] = 0;
    __syncthreads();
    MBAR_WAIT(barE, 0);

    float acc[2][10][4];
#pragma unroll
    for (int t = 0; t < 2; t++)
#pragma unroll
        for (int l = 0; l < 10; l++)
#pragma unroll
            for (int u = 0; u < 4; u++) acc[t][l][u] = 0.f;

    const uint32_t* eI0 = sEi + (size_t)(4 * mh + 0) * EP2W;
    const uint32_t* eI1 = sEi + (size_t)(4 * mh + 1) * EP2W;
    const uint32_t* eI2 = sEi + (size_t)(4 * mh + 2) * EP2W;
    const uint32_t* eI3 = sEi + (size_t)(4 * mh + 3) * EP2W;
    const uint32_t* eJp = sEj + (size_t)gq * EP2W;
    const int bw_off = lane * 44 + nh * 20;
    const bool full_n = (nh == 0);   // nh==1 skips all-zero n-block 19

#define MMA_NBLOCKS(ACC, a0, a1, bp) do { \
        _Pragma("unroll") \
        for (int m = 0; m < 4; m++) { \
            uint4 bb = *(const uint4*)((bp) + m * 4); \
            uint32_t b0[2] = { bb.x, bb.y }; \
            uint32_t b1r[2] = { bb.z, bb.w }; \
            mma16816(ACC[0][2 * m],     a0, b0,  ACC[0][2 * m]); \
            mma16816(ACC[1][2 * m],     a1, b0,  ACC[1][2 * m]); \
            mma16816(ACC[0][2 * m + 1], a0, b1r, ACC[0][2 * m + 1]); \
            mma16816(ACC[1][2 * m + 1], a1, b1r, ACC[1][2 * m + 1]); \
        } \
        { \
            uint4 bb = *(const uint4*)((bp) + 16); \
            uint32_t b0[2] = { bb.x, bb.y }; \
            mma16816(ACC[0][8], a0, b0, ACC[0][8]); \
            mma16816(ACC[1][8], a1, b0, ACC[1][8]); \
            if (full_n) { \
                uint32_t b1r[2] = { bb.z, bb.w }; \
                mma16816(ACC[0][9], a0, b1r, ACC[0][9]); \
                mma16816(ACC[1][9], a1, b1r, ACC[1][9]); \
            } \
        } \
    } while (0)

    // ---- layer 1: 24 slabs of 2 k16-steps; ONE uint4 E load per row per slab ----
    for (int f = 0; f < 24; f++) {
        const int buf = f & 3;
        const uint32_t bw = barW0 + 8 * buf, bc = barC0 + 8 * buf;
        MBAR_WAIT(bw, (f >> 2) & 1);
        const uint32_t* Wb = sWr + buf * SLAB_W;
        {
            int eb = f * 16 + 4 * qq;
            uint4 ejv = *(const uint4*)(eJp + eb);
            uint4 e0v = *(const uint4*)(eI0 + eb);
            uint4 e1v = *(const uint4*)(eI1 + eb);
            uint4 e2v = *(const uint4*)(eI2 + eb);
            uint4 e3v = *(const uint4*)(eI3 + eb);
            {   // ks 0: words .x (h0), .y (h1)
                uint32_t a0[4] = { bmul2(e0v.x, ejv.x), bmul2(e1v.x, ejv.x),
                                   bmul2(e0v.y, ejv.y), bmul2(e1v.y, ejv.y) };
                uint32_t a1[4] = { bmul2(e2v.x, ejv.x), bmul2(e3v.x, ejv.x),
                                   bmul2(e2v.y, ejv.y), bmul2(e3v.y, ejv.y) };
                MMA_NBLOCKS(acc, a0, a1, Wb + bw_off);
            }
            {   // ks 1: words .z (h0), .w (h1)
                uint32_t a0[4] = { bmul2(e0v.z, ejv.z), bmul2(e1v.z, ejv.z),
                                   bmul2(e0v.w, ejv.w), bmul2(e1v.w, ejv.w) };
                uint32_t a1[4] = { bmul2(e2v.z, ejv.z), bmul2(e3v.z, ejv.z),
                                   bmul2(e2v.w, ejv.w), bmul2(e3v.w, ejv.w) };
                MMA_NBLOCKS(acc, a0, a1, Wb + PKS + bw_off);
            }
        }
        __syncwarp();
        if (lane == 0) MBAR_ARRIVE(bc);
        if (w == 0 && lane == 0) {
            MBAR_WAIT(bc, (f >> 2) & 1);
            int nf = f + 4;
            const uint32_t* src = (nf < 24) ? g_w1cP + (size_t)nf * SLAB_W
                                            : g_w2P + (size_t)(nf - 24) * SLAB_W;
            MBAR_EXPECT_TX(bw, SLAB_W * 4);
            bulk_g2s(smem_u32(sWr + buf * SLAB_W), src, SLAB_W * 4, bw);
        }
    }

    // ---- epilogue 1: + seeds (L2 gmem), ReLU, bf16 -> sH1 ----
    {
        const float* Bj = g_B + ((size_t)bz * 192 + tj * 8 + gq) * APITCH;
#pragma unroll
        for (int t = 0; t < 2; t++) {
            const float* A0 = g_A + ((size_t)bz * 192 + ti * 12 + 4 * mh + 2 * t) * APITCH;
            const float* A1 = A0 + APITCH;
#pragma unroll
            for (int l = 0; l < 10; l++) {
                if (l == 9 && !full_n) break;    // dead n-block; pad words pre-zeroed
                int nbg = nh * 10 + l;
                int h0 = nbg * 8 + 2 * qq;
                float v0 = 0.f, v1 = 0.f, v2 = 0.f, v3 = 0.f;
                if (h0 < HH) {
                    float2 a0v = *(const float2*)(A0 + h0);
                    float2 a1v = *(const float2*)(A1 + h0);
                    float2 bjv = *(const float2*)(Bj + h0);
                    v0 = fmaxf(acc[t][l][0] + a0v.x + bjv.x, 0.f);
                    v1 = fmaxf(acc[t][l][1] + a0v.y + bjv.y, 0.f);
                    v2 = fmaxf(acc[t][l][2] + a1v.x + bjv.x, 0.f);
                    v3 = fmaxf(acc[t][l][3] + a1v.y + bjv.y, 0.f);
                }
                int kw = nbg * 4 + qq;
                int ilvw = ((kw >> 3) << 3) + 2 * (kw & 3) + ((kw >> 2) & 1);
                sH1[(32 * mh + 16 * t + gq) * H1PITCH + ilvw]     = packbf(v0, v1);
                sH1[(32 * mh + 16 * t + 8 + gq) * H1PITCH + ilvw] = packbf(v2, v3);
            }
        }
    }
    NBAR(1 + mh, 64);          // nh-pair exchange of h1 halves

    // ---- layer 2: K=160 = fetch slots f=24..28 (2 ks each) ----
    float ac2[2][10][4];
#pragma unroll
    for (int t = 0; t < 2; t++)
#pragma unroll
        for (int l = 0; l < 10; l++)
#pragma unroll
            for (int u = 0; u < 4; u++) ac2[t][l][u] = 0.f;

    const uint32_t* h0p = sH1 + (size_t)(32 * mh + gq) * H1PITCH;
    const uint32_t* h1p = h0p + 8 * H1PITCH;
    const uint32_t* h2p = h0p + 16 * H1PITCH;
    const uint32_t* h3p = h0p + 24 * H1PITCH;

#pragma unroll
    for (int f = 24; f < 29; f++) {
        const int buf = f & 3;
        const uint32_t bw = barW0 + 8 * buf, bc = barC0 + 8 * buf;
        MBAR_WAIT(bw, (f >> 2) & 1);
        const uint32_t* Wb = sWr + buf * SLAB_W;
#pragma unroll
        for (int ks2 = 0; ks2 < 2; ks2++) {
            int kb = (f - 24) * 16 + ks2 * 8 + 2 * qq;
            uint2 x0 = *(const uint2*)(h0p + kb);
            uint2 x1 = *(const uint2*)(h1p + kb);
            uint2 x2 = *(const uint2*)(h2p + kb);
            uint2 x3 = *(const uint2*)(h3p + kb);
            uint32_t a0[4] = { x0.x, x1.x, x0.y, x1.y };
            uint32_t a1[4] = { x2.x, x3.x, x2.y, x3.y };
            const uint32_t* bp = Wb + ks2 * PKS + bw_off;
            MMA_NBLOCKS(ac2, a0, a1, bp);
        }
        if (f == 24) {   // refill f=28 (W2 ks 8-9) into buf0 once all warps consumed f=24
            __syncwarp();
            if (lane == 0) MBAR_ARRIVE(bc);
            if (w == 0 && lane == 0) {
                MBAR_WAIT(bc, (f >> 2) & 1);
                MBAR_EXPECT_TX(bw, SLAB_W * 4);
                bulk_g2s(smem_u32(sWr + buf * SLAB_W), g_w2P + (size_t)4 * SLAB_W,
                         SLAB_W * 4, bw);
            }
        }
    }

    // ---- epilogue 2: +b2, ReLU, dot W3; partials to g_S / g_S2 (no exchange) ----
    float sp[2][2] = { {0.f, 0.f}, {0.f, 0.f} };
#pragma unroll
    for (int t = 0; t < 2; t++)
#pragma unroll
        for (int l = 0; l < 10; l++) {
            if (l == 9 && !full_n) break;
            int h0 = (nh * 10 + l) * 8 + 2 * qq;
            if (h0 < HH) {
                float2 bv = *(const float2*)(sB2 + h0);
                float2 wv = *(const float2*)(sW3 + h0);
                sp[t][0] += fmaxf(ac2[t][l][0] + bv.x, 0.f) * wv.x
                          + fmaxf(ac2[t][l][1] + bv.y, 0.f) * wv.y;
                sp[t][1] += fmaxf(ac2[t][l][2] + bv.x, 0.f) * wv.x
                          + fmaxf(ac2[t][l][3] + bv.y, 0.f) * wv.y;
            }
        }
#pragma unroll
    for (int t = 0; t < 2; t++)
#pragma unroll
        for (int s = 0; s < 2; s++) {
            sp[t][s] += __shfl_xor_sync(0xffffffffu, sp[t][s], 1);
            sp[t][s] += __shfl_xor_sync(0xffffffffu, sp[t][s], 2);
        }
    if (qq == 0) {
        float* dst = full_n ? g_S2 : g_S;
#pragma unroll
        for (int t = 0; t < 2; t++)
#pragma unroll
            for (int s = 0; s < 2; s++) {
                int r = 32 * mh + 16 * t + 8 * s + gq;
                int ip = ti * 12 + (r >> 3), jp = tj * 8 + (r & 7);
                if (jp < ip)
                    dst[((size_t)bz * 192 + ip) * 192 + jp] = sp[t][s];
            }
    }
}

// ---------------- k3: tril softmax (sums the two partial-score arrays) ----------------
__global__ void k3_softmax(float* __restrict__ out, const float* __restrict__ b3) {
    const int i = blockIdx.x, b = blockIdx.y, j = threadIdx.x;
    const float b3v = __ldg(b3);
    float val;
    if (j < i) {
        size_t idx = ((size_t)b * 192 + i) * 192 + j;
        val = g_S[idx] + g_S2[idx] + b3v;
    } else if (j == i) val = 0.f;
    else               val = -1e30f;

    __shared__ float red[6];
    float m = val;
#pragma unroll
    for (int o = 16; o; o >>= 1) m = fmaxf(m, __shfl_xor_sync(0xffffffffu, m, o));
    if ((j & 31) == 0) red[j >> 5] = m;
    __syncthreads();
    float M = fmaxf(fmaxf(fmaxf(red[0], red[1]), fmaxf(red[2], red[3])), fmaxf(red[4], red[5]));
    __syncthreads();
    float e = (j <= i) ? expf(val - M) : 0.f;
    float s = e;
#pragma unroll
    for (int o = 16; o; o >>= 1) s += __shfl_xor_sync(0xffffffffu, s, o);
    if ((j & 31) == 0) red[j >> 5] = s;
    __syncthreads();
    float S = red[0] + red[1] + red[2] + red[3] + red[4] + red[5];
    out[((size_t)b * 192 + i) * 192 + j] = (j <= i) ? (e / S) : -1000.0f;
}

// ---------------------------------------------------------------------------
extern "C" void kernel_launch(void* const* d_in, const int* in_sizes, int n_in,
                              void* d_out, int out_size) {
    const float* E  = (const float*)d_in[0];
    const float* W1 = (const float*)d_in[1];
    const float* b1 = (const float*)d_in[2];
    const float* W2 = (const float*)d_in[3];
    const float* b2 = (const float*)d_in[4];
    const float* W3 = (const float*)d_in[5];
    const float* b3 = (const float*)d_in[6];
    float* out = (float*)d_out;

    cudaFuncSetAttribute(k1_mma, cudaFuncAttributeMaxDynamicSharedMemorySize, K1_SMEM);
    cudaFuncSetAttribute(k2_mma, cudaFuncAttributeMaxDynamicSharedMemorySize, K2_SMEM);

    const int prep_n = PE_N + PE2_N + WAB_N + W1C_WORDS + W2_WORDS;
    kprep<<<(prep_n + 255) / 256, 256>>>(E, W1, W2);
    k1_mma<<<48, 256, K1_SMEM>>>(b1);
    k2_mma<<<dim3(208, 8), 192, K2_SMEM>>>(b2, W3);
    k3_softmax<<<dim3(192, 8), 192>>>(out, b3);
}

// round 15
// speedup vs baseline: 1.2154x; 1.0182x over previous
#include <cuda_runtime.h>
#include <cuda_bf16.h>
#include <cstdint>

#define HH 150
#define APITCH 152          // g_A/g_B row pitch (floats)

#define EPITCH 392          // E row pitch in u32 words
#define H1PITCH 88          // h1 row pitch in u32 words
#define WABPITCH 36         // k1 weight row pitch (u32 words)

// Packed-fragment W blob geometry: per k16-step: 32 lanes * 44 words
#define PKS 1408
#define W1C_WORDS (48 * PKS)
#define W2_WORDS  (10 * PKS)
#define SLAB_W (2 * PKS)    // 2 ks per fetch slab (11264 B)

// ---------------- device scratch ----------------
__device__ __align__(16) uint32_t      g_Ebf[1536 * EPITCH];
__device__ __align__(16) __nv_bfloat16 g_wabT[12 * 320 * 72];
__device__ __align__(16) uint32_t      g_w1cP[W1C_WORDS];
__device__ __align__(16) uint32_t      g_w2P[W2_WORDS];
__device__ __align__(16) float g_A[1536 * APITCH];
__device__ __align__(16) float g_B[1536 * APITCH];
__device__ float g_S[8 * 192 * 192];
__device__ float g_S2[8 * 192 * 192];

// ---------------- helpers ----------------
__device__ __forceinline__ uint32_t smem_u32(const void* p) {
    uint32_t a;
    asm("{ .reg .u64 t; cvta.to.shared.u64 t, %1; cvt.u32.u64 %0, t; }" : "=r"(a) : "l"(p));
    return a;
}
__device__ __forceinline__ uint32_t packbf(float lo, float hi) {
    uint32_t d; asm("cvt.rn.bf16x2.f32 %0, %1, %2;" : "=r"(d) : "f"(hi), "f"(lo)); return d;
}
__device__ __forceinline__ uint32_t bmul2(uint32_t a, uint32_t b) {
    uint32_t d; asm("mul.rn.bf16x2 %0, %1, %2;" : "=r"(d) : "r"(a), "r"(b)); return d;
}
__device__ __forceinline__ void mma16816(float* d, const uint32_t* a, const uint32_t* b,
                                         const float* c) {
    asm volatile(
        "mma.sync.aligned.m16n8k16.row.col.f32.bf16.bf16.f32 "
        "{%0,%1,%2,%3}, {%4,%5,%6,%7}, {%8,%9}, {%10,%11,%12,%13};"
        : "=f"(d[0]), "=f"(d[1]), "=f"(d[2]), "=f"(d[3])
        : "r"(a[0]), "r"(a[1]), "r"(a[2]), "r"(a[3]), "r"(b[0]), "r"(b[1]),
          "f"(c[0]), "f"(c[1]), "f"(c[2]), "f"(c[3]));
}
#define MBAR_INIT(mb, cnt) asm volatile("mbarrier.init.shared.b64 [%0], %1;" :: "r"((uint32_t)(mb)), "r"((uint32_t)(cnt)) : "memory")
#define MBAR_EXPECT_TX(mb, n) asm volatile("mbarrier.arrive.expect_tx.shared.b64 _, [%0], %1;" :: "r"((uint32_t)(mb)), "r"((uint32_t)(n)) : "memory")
#define MBAR_ARRIVE(mb) asm volatile("mbarrier.arrive.release.cta.shared::cta.b64 _, [%0];" :: "r"((uint32_t)(mb)) : "memory")
#define FENCE_ASYNC() asm volatile("fence.proxy.async.shared::cta;" ::: "memory")
#define NBAR(id, cnt) asm volatile("bar.sync %0, %1;" :: "r"(id), "r"(cnt) : "memory")
#define MBAR_WAIT(mb, ph) do { \
    uint32_t _m = (uint32_t)(mb); uint32_t _p = (uint32_t)(ph); uint32_t _d; \
    asm volatile("{\n\t.reg .pred p;\n\tmbarrier.try_wait.parity.acquire.cta.shared::cta.b64 p, [%1], %2;\n\tselp.b32 %0, 1, 0, p;\n\t}" \
        : "=r"(_d) : "r"(_m), "r"(_p) : "memory"); \
    if (!_d) { \
        asm volatile("{\n\t.reg .pred P1;\n\tWL_%=:\n\tmbarrier.try_wait.parity.acquire.cta.shared::cta.b64 P1, [%0], %1, 0x989680;\n\t@P1 bra.uni WD_%=;\n\tbra.uni WL_%=;\n\tWD_%=:\n\t}" \
            :: "r"(_m), "r"(_p) : "memory"); \
    } } while (0)
__device__ __forceinline__ void bulk_g2s(uint32_t dst, const void* src, uint32_t bytes, uint32_t mbar) {
    asm volatile("cp.async.bulk.shared::cta.global.mbarrier::complete_tx::bytes [%0], [%1], %2, [%3];"
        :: "r"(dst), "l"(src), "r"(bytes), "r"(mbar) : "memory");
}

// ---------------- merged prep: E repack + weight repack (one launch) ----------------
#define PE_N  (1536 * EPITCH)
#define WAB_N (12 * 320 * 72)
__global__ void kprep(const float* __restrict__ E,
                      const float* __restrict__ W1, const float* __restrict__ W2) {
    int idx = blockIdx.x * 256 + threadIdx.x;
    if (idx < PE_N) {
        int r = idx / EPITCH, pos = idx % EPITCH;
        int g = pos >> 3, wi = pos & 7, q = wi >> 1, h = wi & 1;
        int kw = g * 8 + q + 4 * h;
        uint32_t v = 0;
        if (kw < 384) {
            float2 e = *reinterpret_cast<const float2*>(E + (size_t)r * 768 + 2 * kw);
            v = packbf(e.x, e.y);
        }
        g_Ebf[idx] = v;
    } else if (idx < PE_N + WAB_N) {
        int t = idx - PE_N;
        int c = t / (320 * 72), rem = t % (320 * 72);
        int n = rem / 72, kk = rem % 72;
        float v = 0.f;
        if (kk < 64) {
            int kg = c * 64 + kk;
            if (n < 160) { if (n < HH) v = W1[(size_t)kg * HH + n]; }
            else { int h = n - 160; if (h < HH) v = W1[(size_t)(768 + kg) * HH + h]; }
        }
        g_wabT[t] = __float2bfloat16(v);
    } else if (idx < PE_N + WAB_N + W1C_WORDS + W2_WORDS) {
        int t = idx - PE_N - WAB_N;
        bool isW2 = (t >= W1C_WORDS);
        int r = isW2 ? (t - W1C_WORDS) : t;
        int ks = r / PKS, r1 = r % PKS;
        int lane = r1 / 44, r2 = r1 % 44;
        uint32_t v = 0;
        if (r2 < 40) {
            int nh = r2 / 20, r3 = r2 % 20, m = r3 / 4, e = r3 % 4;
            int gq = lane >> 2, qq = lane & 3;
            int nb = nh * 10 + 2 * m + (e >> 1);
            int kwl = ks * 8 + qq + (e & 1) * 4;
            int n = nb * 8 + gq;
            float v0 = 0.f, v1 = 0.f;
            if (n < HH) {
                int k0 = 2 * kwl;
                if (isW2) {
                    if (k0 < HH)     v0 = W2[(size_t)k0 * HH + n];
                    if (k0 + 1 < HH) v1 = W2[(size_t)(k0 + 1) * HH + n];
                } else {
                    v0 = W1[(size_t)(1536 + k0) * HH + n];
                    v1 = W1[(size_t)(1536 + k0 + 1) * HH + n];
                }
            }
            v = packbf(v0, v1);
        }
        if (isW2) g_w2P[r] = v; else g_w1cP[r] = v;
    }
}

// ---------------- k1: seeds GEMM -> g_A,g_B (pitch 152) ----------------
#define K1_E_BYTES (32 * EPITCH * 4)
#define K1_W_BYTES (320 * WABPITCH * 4)
#define K1_BAR_OFF (K1_E_BYTES + 2 * K1_W_BYTES)
#define K1_SMEM    (K1_BAR_OFF + 64)

__global__ __launch_bounds__(256, 1)
void k1_mma(const float* __restrict__ b1) {
    extern __shared__ __align__(128) char smem[];
    uint32_t* sE = (uint32_t*)smem;
    uint32_t* sW[2] = { (uint32_t*)(smem + K1_E_BYTES),
                        (uint32_t*)(smem + K1_E_BYTES + K1_W_BYTES) };
    const uint32_t barE = smem_u32(smem + K1_BAR_OFF);
    const uint32_t barW[2] = { barE + 8, barE + 16 };
    const int tid = threadIdx.x, w = tid >> 5, lane = tid & 31;
    const int gq = lane >> 2, qq = lane & 3;
    const int r0 = blockIdx.x * 32;

    if (tid == 0) {
        MBAR_INIT(barE, 1); MBAR_INIT(barW[0], 1); MBAR_INIT(barW[1], 1);
        FENCE_ASYNC();
        MBAR_EXPECT_TX(barE, K1_E_BYTES);
        bulk_g2s(smem_u32(sE), g_Ebf + (size_t)r0 * EPITCH, K1_E_BYTES, barE);
        MBAR_EXPECT_TX(barW[0], K1_W_BYTES);
        bulk_g2s(smem_u32(sW[0]), g_wabT, K1_W_BYTES, barW[0]);
        MBAR_EXPECT_TX(barW[1], K1_W_BYTES);
        bulk_g2s(smem_u32(sW[1]), g_wabT + (size_t)320 * 72, K1_W_BYTES, barW[1]);
    }
    __syncthreads();
    MBAR_WAIT(barE, 0);

    float acc[2][5][4];
#pragma unroll
    for (int t = 0; t < 2; t++)
#pragma unroll
        for (int l = 0; l < 5; l++)
#pragma unroll
            for (int u = 0; u < 4; u++) acc[t][l][u] = 0.f;

    const uint32_t* e0p = sE + (size_t)gq * EPITCH;
    const uint32_t* e1p = e0p + 8 * EPITCH;
    const uint32_t* e2p = e0p + 16 * EPITCH;
    const uint32_t* e3p = e0p + 24 * EPITCH;

    for (int c = 0; c < 12; c++) {
        MBAR_WAIT(barW[c & 1], (c >> 1) & 1);
        const uint32_t* Wb = sW[c & 1];
#pragma unroll
        for (int ks = 0; ks < 4; ks++) {
            int kb = c * 32 + ks * 8 + 2 * qq;
            uint2 e0 = *(const uint2*)(e0p + kb);
            uint2 e1 = *(const uint2*)(e1p + kb);
            uint2 e2 = *(const uint2*)(e2p + kb);
            uint2 e3 = *(const uint2*)(e3p + kb);
            uint32_t a0[4] = { e0.x, e1.x, e0.y, e1.y };
            uint32_t a1[4] = { e2.x, e3.x, e2.y, e3.y };
#pragma unroll
            for (int l = 0; l < 5; l++) {
                int nrow = (w * 5 + l) * 8 + gq;
                uint32_t b[2] = { Wb[nrow * WABPITCH + ks * 8 + qq],
                                  Wb[nrow * WABPITCH + ks * 8 + qq + 4] };
                mma16816(acc[0][l], a0, b, acc[0][l]);
                mma16816(acc[1][l], a1, b, acc[1][l]);
            }
        }
        __syncthreads();
        if (tid == 0 && c + 2 < 12) {
            MBAR_EXPECT_TX(barW[c & 1], K1_W_BYTES);
            bulk_g2s(smem_u32(sW[c & 1]), g_wabT + (size_t)(c + 2) * 320 * 72,
                     K1_W_BYTES, barW[c & 1]);
        }
    }

#pragma unroll
    for (int t = 0; t < 2; t++)
#pragma unroll
        for (int l = 0; l < 5; l++) {
            int n0 = (w * 5 + l) * 8 + 2 * qq;
            int ra = r0 + 16 * t + gq, rb = ra + 8;
#pragma unroll
            for (int u = 0; u < 4; u++) {
                int row = (u < 2) ? ra : rb;
                int n = n0 + (u & 1);
                float v = acc[t][l][u];
                if (n < 160) { if (n < HH) g_A[(size_t)row * APITCH + n] = v + __ldg(b1 + n); }
                else { int h = n - 160; if (h < HH) g_B[(size_t)row * APITCH + h] = v; }
            }
        }
}

// ---------------- k2: fused pair MLP, 2 CTAs/SM, 4-deep W ring (round-9 config) ----------------
#define K2_EI_OFF   0                                  // 12*392*4 = 18816
#define K2_EJ_OFF   18816                              // 8*392*4  = 12544
#define K2_W_OFF    31360                              // 4 x 11264 = 45056
#define K2_H1_OFF   76416                              // 96*88*4 = 33792
#define K2_BW_OFF   110208                             // b2|W3: 1216
#define K2_BAR_OFF  111424
#define K2_SMEM     (K2_BAR_OFF + 128)                 // 111552

__global__ __launch_bounds__(192, 2)
void k2_mma(const float* __restrict__ b2,
            const float* __restrict__ W3) {
    const int bz = blockIdx.y;
    const int x = blockIdx.x;
    const int cumt[16] = {0,2,5,10,16,24,33,44,56,70,85,102,120,140,161,184};
    int ti = 0;
#pragma unroll
    for (int t = 1; t < 16; t++)
        if (cumt[t] <= x) ti = t;
    const int tj = x - cumt[ti];

    extern __shared__ __align__(128) char smem[];
    uint32_t* sEi = (uint32_t*)(smem + K2_EI_OFF);
    uint32_t* sEj = (uint32_t*)(smem + K2_EJ_OFF);
    uint32_t* sWr = (uint32_t*)(smem + K2_W_OFF);      // ring: 4 x SLAB_W
    uint32_t* sH1 = (uint32_t*)(smem + K2_H1_OFF);
    float*    sB2 = (float*)(smem + K2_BW_OFF);
    float*    sW3 = sB2 + 152;
    const uint32_t barE = smem_u32(smem + K2_BAR_OFF);
    const uint32_t barW0 = barE + 8;    // barW[b] = barW0 + 8b
    const uint32_t barC0 = barE + 40;   // barC[b] = barC0 + 8b
    const int tid = threadIdx.x, w = tid >> 5, lane = tid & 31;
    const int mh = w >> 1, nh = w & 1;
    const int gq = lane >> 2, qq = lane & 3;

    if (tid == 0) {
        MBAR_INIT(barE, 1);
#pragma unroll
        for (int b = 0; b < 4; b++) { MBAR_INIT(barW0 + 8 * b, 1); MBAR_INIT(barC0 + 8 * b, 6); }
        FENCE_ASYNC();
        MBAR_EXPECT_TX(barE, (12 + 8) * EPITCH * 4);
        bulk_g2s(smem_u32(sEi), g_Ebf + ((size_t)bz * 192 + ti * 12) * EPITCH, 12 * EPITCH * 4, barE);
        bulk_g2s(smem_u32(sEj), g_Ebf + ((size_t)bz * 192 + tj * 8) * EPITCH, 8 * EPITCH * 4, barE);
#pragma unroll
        for (int f = 0; f < 4; f++) {
            MBAR_EXPECT_TX(barW0 + 8 * f, SLAB_W * 4);
            bulk_g2s(smem_u32(sWr + f * SLAB_W), g_w1cP + (size_t)f * SLAB_W, SLAB_W * 4, barW0 + 8 * f);
        }
    }
    // stage b2/W3; zero sH1 pad words kw 76..79 (read by L2 ks9 against zero weights)
    for (int idx = tid; idx < 304; idx += 192) {
        if (idx < 152) sB2[idx] = (idx < HH) ? b2[idx] : 0.f;
        else { int h = idx - 152; sW3[h] = (h < HH) ? W3[h] : 0.f; }
    }
    for (int idx = tid; idx < 96 * 4; idx += 192)
        sH1[(idx >> 2) * H1PITCH + 76 + (idx & 3)] = 0;
    __syncthreads();
    MBAR_WAIT(barE, 0);

    float acc[2][10][4];
#pragma unroll
    for (int t = 0; t < 2; t++)
#pragma unroll
        for (int l = 0; l < 10; l++)
#pragma unroll
            for (int u = 0; u < 4; u++) acc[t][l][u] = 0.f;

    const uint32_t* eI0 = sEi + (size_t)(4 * mh + 0) * EPITCH;
    const uint32_t* eI1 = sEi + (size_t)(4 * mh + 1) * EPITCH;
    const uint32_t* eI2 = sEi + (size_t)(4 * mh + 2) * EPITCH;
    const uint32_t* eI3 = sEi + (size_t)(4 * mh + 3) * EPITCH;
    const uint32_t* eJp = sEj + (size_t)gq * EPITCH;
    const int bw_off = lane * 44 + nh * 20;
    const bool full_n = (nh == 0);   // nh==1 skips all-zero n-block 19

#define MMA_NBLOCKS(ACC, a0, a1, bp) do { \
        _Pragma("unroll") \
        for (int m = 0; m < 4; m++) { \
            uint4 bb = *(const uint4*)((bp) + m * 4); \
            uint32_t b0[2] = { bb.x, bb.y }; \
            uint32_t b1r[2] = { bb.z, bb.w }; \
            mma16816(ACC[0][2 * m],     a0, b0,  ACC[0][2 * m]); \
            mma16816(ACC[1][2 * m],     a1, b0,  ACC[1][2 * m]); \
            mma16816(ACC[0][2 * m + 1], a0, b1r, ACC[0][2 * m + 1]); \
            mma16816(ACC[1][2 * m + 1], a1, b1r, ACC[1][2 * m + 1]); \
        } \
        { \
            uint4 bb = *(const uint4*)((bp) + 16); \
            uint32_t b0[2] = { bb.x, bb.y }; \
            mma16816(ACC[0][8], a0, b0, ACC[0][8]); \
            mma16816(ACC[1][8], a1, b0, ACC[1][8]); \
            if (full_n) { \
                uint32_t b1r[2] = { bb.z, bb.w }; \
                mma16816(ACC[0][9], a0, b1r, ACC[0][9]); \
                mma16816(ACC[1][9], a1, b1r, ACC[1][9]); \
            } \
        } \
    } while (0)

    // ---- layer 1: 24 slabs of 2 k16-steps through the 4-buffer ring ----
    for (int f = 0; f < 24; f++) {
        const int buf = f & 3;
        const uint32_t bw = barW0 + 8 * buf, bc = barC0 + 8 * buf;
        MBAR_WAIT(bw, (f >> 2) & 1);
        const uint32_t* Wb = sWr + buf * SLAB_W;
#pragma unroll
        for (int ks = 0; ks < 2; ks++) {
            int kb = f * 16 + ks * 8 + 2 * qq;
            uint2 ej = *(const uint2*)(eJp + kb);
            uint2 e0 = *(const uint2*)(eI0 + kb);
            uint2 e1 = *(const uint2*)(eI1 + kb);
            uint2 e2 = *(const uint2*)(eI2 + kb);
            uint2 e3 = *(const uint2*)(eI3 + kb);
            uint32_t a0[4] = { bmul2(e0.x, ej.x), bmul2(e1.x, ej.x),
                               bmul2(e0.y, ej.y), bmul2(e1.y, ej.y) };
            uint32_t a1[4] = { bmul2(e2.x, ej.x), bmul2(e3.x, ej.x),
                               bmul2(e2.y, ej.y), bmul2(e3.y, ej.y) };
            const uint32_t* bp = Wb + ks * PKS + bw_off;
            MMA_NBLOCKS(acc, a0, a1, bp);
        }
        __syncwarp();
        if (lane == 0) MBAR_ARRIVE(bc);
        if (w == 0 && lane == 0) {
            MBAR_WAIT(bc, (f >> 2) & 1);
            int nf = f + 4;
            const uint32_t* src = (nf < 24) ? g_w1cP + (size_t)nf * SLAB_W
                                            : g_w2P + (size_t)(nf - 24) * SLAB_W;
            MBAR_EXPECT_TX(bw, SLAB_W * 4);
            bulk_g2s(smem_u32(sWr + buf * SLAB_W), src, SLAB_W * 4, bw);
        }
    }

    // ---- epilogue 1: + seeds (L2 gmem), ReLU, bf16 -> sH1 ----
    {
        const float* Bj = g_B + ((size_t)bz * 192 + tj * 8 + gq) * APITCH;
#pragma unroll
        for (int t = 0; t < 2; t++) {
            const float* A0 = g_A + ((size_t)bz * 192 + ti * 12 + 4 * mh + 2 * t) * APITCH;
            const float* A1 = A0 + APITCH;
#pragma unroll
            for (int l = 0; l < 10; l++) {
                if (l == 9 && !full_n) break;    // dead n-block; pad pre-zeroed
                int nbg = nh * 10 + l;
                int h0 = nbg * 8 + 2 * qq;
                float v0 = 0.f, v1 = 0.f, v2 = 0.f, v3 = 0.f;
                if (h0 < HH) {
                    float2 a0v = *(const float2*)(A0 + h0);
                    float2 a1v = *(const float2*)(A1 + h0);
                    float2 bjv = *(const float2*)(Bj + h0);
                    v0 = fmaxf(acc[t][l][0] + a0v.x + bjv.x, 0.f);
                    v1 = fmaxf(acc[t][l][1] + a0v.y + bjv.y, 0.f);
                    v2 = fmaxf(acc[t][l][2] + a1v.x + bjv.x, 0.f);
                    v3 = fmaxf(acc[t][l][3] + a1v.y + bjv.y, 0.f);
                }
                int kw = nbg * 4 + qq;
                int ilvw = ((kw >> 3) << 3) + 2 * (kw & 3) + ((kw >> 2) & 1);
                sH1[(32 * mh + 16 * t + gq) * H1PITCH + ilvw]     = packbf(v0, v1);
                sH1[(32 * mh + 16 * t + 8 + gq) * H1PITCH + ilvw] = packbf(v2, v3);
            }
        }
    }
    NBAR(1 + mh, 64);          // nh-pair exchange of h1 halves

    // ---- layer 2: K=160 = fetch slots f=24..28 (2 ks each) ----
    float ac2[2][10][4];
#pragma unroll
    for (int t = 0; t < 2; t++)
#pragma unroll
        for (int l = 0; l < 10; l++)
#pragma unroll
            for (int u = 0; u < 4; u++) ac2[t][l][u] = 0.f;

    const uint32_t* h0p = sH1 + (size_t)(32 * mh + gq) * H1PITCH;
    const uint32_t* h1p = h0p + 8 * H1PITCH;
    const uint32_t* h2p = h0p + 16 * H1PITCH;
    const uint32_t* h3p = h0p + 24 * H1PITCH;

#pragma unroll
    for (int f = 24; f < 29; f++) {
        const int buf = f & 3;
        const uint32_t bw = barW0 + 8 * buf, bc = barC0 + 8 * buf;
        MBAR_WAIT(bw, (f >> 2) & 1);
        const uint32_t* Wb = sWr + buf * SLAB_W;
#pragma unroll
        for (int ks2 = 0; ks2 < 2; ks2++) {
            int kb = (f - 24) * 16 + ks2 * 8 + 2 * qq;
            uint2 x0 = *(const uint2*)(h0p + kb);
            uint2 x1 = *(const uint2*)(h1p + kb);
            uint2 x2 = *(const uint2*)(h2p + kb);
            uint2 x3 = *(const uint2*)(h3p + kb);
            uint32_t a0[4] = { x0.x, x1.x, x0.y, x1.y };
            uint32_t a1[4] = { x2.x, x3.x, x2.y, x3.y };
            const uint32_t* bp = Wb + ks2 * PKS + bw_off;
            MMA_NBLOCKS(ac2, a0, a1, bp);
        }
        if (f == 24) {   // refill f=28 (W2 ks 8-9) into buf0 once all warps consumed f=24
            __syncwarp();
            if (lane == 0) MBAR_ARRIVE(bc);
            if (w == 0 && lane == 0) {
                MBAR_WAIT(bc, (f >> 2) & 1);
                MBAR_EXPECT_TX(bw, SLAB_W * 4);
                bulk_g2s(smem_u32(sWr + buf * SLAB_W), g_w2P + (size_t)4 * SLAB_W,
                         SLAB_W * 4, bw);
            }
        }
    }

    // ---- epilogue 2: +b2, ReLU, dot W3; partials to g_S / g_S2 (no exchange) ----
    float sp[2][2] = { {0.f, 0.f}, {0.f, 0.f} };
#pragma unroll
    for (int t = 0; t < 2; t++)
#pragma unroll
        for (int l = 0; l < 10; l++) {
            if (l == 9 && !full_n) break;
            int h0 = (nh * 10 + l) * 8 + 2 * qq;
            if (h0 < HH) {
                float2 bv = *(const float2*)(sB2 + h0);
                float2 wv = *(const float2*)(sW3 + h0);
                sp[t][0] += fmaxf(ac2[t][l][0] + bv.x, 0.f) * wv.x
                          + fmaxf(ac2[t][l][1] + bv.y, 0.f) * wv.y;
                sp[t][1] += fmaxf(ac2[t][l][2] + bv.x, 0.f) * wv.x
                          + fmaxf(ac2[t][l][3] + bv.y, 0.f) * wv.y;
            }
        }
#pragma unroll
    for (int t = 0; t < 2; t++)
#pragma unroll
        for (int s = 0; s < 2; s++) {
            sp[t][s] += __shfl_xor_sync(0xffffffffu, sp[t][s], 1);
            sp[t][s] += __shfl_xor_sync(0xffffffffu, sp[t][s], 2);
        }
    if (qq == 0) {
        float* dst = full_n ? g_S2 : g_S;
#pragma unroll
        for (int t = 0; t < 2; t++)
#pragma unroll
            for (int s = 0; s < 2; s++) {
                int r = 32 * mh + 16 * t + 8 * s + gq;
                int ip = ti * 12 + (r >> 3), jp = tj * 8 + (r & 7);
                if (jp < ip)
                    dst[((size_t)bz * 192 + ip) * 192 + jp] = sp[t][s];
            }
    }
}

// ---------------- k3: warp-per-row tril softmax (barrier-free) ----------------
// grid 192, block 256 (8 warps). Warp handles row = blockIdx.x*8 + warp.
__global__ __launch_bounds__(256, 4)
void k3_softmax(float* __restrict__ out, const float* __restrict__ b3) {
    const int w = threadIdx.x >> 5, lane = threadIdx.x & 31;
    const int row = blockIdx.x * 8 + w;            // 0..1535
    const int i = row & 191;                       // row % 192 (192 = 64*3; use mod)
    const int ii = row - (row / 192) * 192;
    const float b3v = __ldg(b3);
    (void)i;

    float v[6];
    float m = -1e30f;
#pragma unroll
    for (int k = 0; k < 6; k++) {
        int j = lane + 32 * k;
        float val;
        if (j < ii) {
            size_t idx = (size_t)row * 192 + j;
            val = g_S[idx] + g_S2[idx] + b3v;
        } else if (j == ii) val = 0.f;
        else                val = -1e30f;
        v[k] = val;
        m = fmaxf(m, val);
    }
#pragma unroll
    for (int o = 16; o; o >>= 1) m = fmaxf(m, __shfl_xor_sync(0xffffffffu, m, o));

    float s = 0.f;
#pragma unroll
    for (int k = 0; k < 6; k++) {
        int j = lane + 32 * k;
        v[k] = (j <= ii) ? expf(v[k] - m) : 0.f;
        s += v[k];
    }
#pragma unroll
    for (int o = 16; o; o >>= 1) s += __shfl_xor_sync(0xffffffffu, s, o);
    float inv = 1.f / s;

#pragma unroll
    for (int k = 0; k < 6; k++) {
        int j = lane + 32 * k;
        out[(size_t)row * 192 + j] = (j <= ii) ? (v[k] * inv) : -1000.0f;
    }
}

// ---------------------------------------------------------------------------
extern "C" void kernel_launch(void* const* d_in, const int* in_sizes, int n_in,
                              void* d_out, int out_size) {
    const float* E  = (const float*)d_in[0];
    const float* W1 = (const float*)d_in[1];
    const float* b1 = (const float*)d_in[2];
    const float* W2 = (const float*)d_in[3];
    const float* b2 = (const float*)d_in[4];
    const float* W3 = (const float*)d_in[5];
    const float* b3 = (const float*)d_in[6];
    float* out = (float*)d_out;

    cudaFuncSetAttribute(k1_mma, cudaFuncAttributeMaxDynamicSharedMemorySize, K1_SMEM);
    cudaFuncSetAttribute(k2_mma, cudaFuncAttributeMaxDynamicSharedMemorySize, K2_SMEM);

    const int prep_n = PE_N + WAB_N + W1C_WORDS + W2_WORDS;
    kprep<<<(prep_n + 255) / 256, 256>>>(E, W1, W2);
    k1_mma<<<48, 256, K1_SMEM>>>(b1);
    k2_mma<<<dim3(208, 8), 192, K2_SMEM>>>(b2, W3);
    k3_softmax<<<192, 256>>>(out, b3);
}

// round 16
// speedup vs baseline: 1.3249x; 1.0901x over previous
#include <cuda_runtime.h>
#include <cuda_bf16.h>
#include <cstdint>

#define HH 150
#define APITCH 152          // g_A/g_B row pitch (floats)

#define EPITCH 392          // E row pitch in u32 words
#define H1PITCH 88          // h1 row pitch in u32 words
#define WABPITCH 36         // k1 weight row pitch (u32 words)

// Packed-fragment W blob geometry: per k16-step: 32 lanes * 44 words
#define PKS 1408
#define W1C_WORDS (48 * PKS)
#define W2_WORDS  (10 * PKS)
#define SLAB_W (2 * PKS)    // 2 ks per fetch slab (11264 B)

// ---------------- device scratch ----------------
__device__ __align__(16) uint32_t      g_Ebf[1536 * EPITCH];
__device__ __align__(16) __nv_bfloat16 g_wabT[12 * 320 * 72];
__device__ __align__(16) uint32_t      g_w1cP[W1C_WORDS];
__device__ __align__(16) uint32_t      g_w2P[W2_WORDS];
__device__ __align__(16) float g_A[1536 * APITCH];
__device__ __align__(16) float g_B[1536 * APITCH];
__device__ float g_S[8 * 192 * 192];
__device__ float g_S2[8 * 192 * 192];

// ---------------- helpers ----------------
__device__ __forceinline__ uint32_t smem_u32(const void* p) {
    uint32_t a;
    asm("{ .reg .u64 t; cvta.to.shared.u64 t, %1; cvt.u32.u64 %0, t; }" : "=r"(a) : "l"(p));
    return a;
}
__device__ __forceinline__ uint32_t packbf(float lo, float hi) {
    uint32_t d; asm("cvt.rn.bf16x2.f32 %0, %1, %2;" : "=r"(d) : "f"(hi), "f"(lo)); return d;
}
__device__ __forceinline__ uint32_t bmul2(uint32_t a, uint32_t b) {
    uint32_t d; asm("mul.rn.bf16x2 %0, %1, %2;" : "=r"(d) : "r"(a), "r"(b)); return d;
}
__device__ __forceinline__ void mma16816(float* d, const uint32_t* a, const uint32_t* b,
                                         const float* c) {
    asm volatile(
        "mma.sync.aligned.m16n8k16.row.col.f32.bf16.bf16.f32 "
        "{%0,%1,%2,%3}, {%4,%5,%6,%7}, {%8,%9}, {%10,%11,%12,%13};"
        : "=f"(d[0]), "=f"(d[1]), "=f"(d[2]), "=f"(d[3])
        : "r"(a[0]), "r"(a[1]), "r"(a[2]), "r"(a[3]), "r"(b[0]), "r"(b[1]),
          "f"(c[0]), "f"(c[1]), "f"(c[2]), "f"(c[3]));
}
#define GDC_WAIT()   asm volatile("griddepcontrol.wait;" ::: "memory")
#define GDC_LAUNCH() asm volatile("griddepcontrol.launch_dependents;")
#define MBAR_INIT(mb, cnt) asm volatile("mbarrier.init.shared.b64 [%0], %1;" :: "r"((uint32_t)(mb)), "r"((uint32_t)(cnt)) : "memory")
#define MBAR_EXPECT_TX(mb, n) asm volatile("mbarrier.arrive.expect_tx.shared.b64 _, [%0], %1;" :: "r"((uint32_t)(mb)), "r"((uint32_t)(n)) : "memory")
#define MBAR_ARRIVE(mb) asm volatile("mbarrier.arrive.release.cta.shared::cta.b64 _, [%0];" :: "r"((uint32_t)(mb)) : "memory")
#define FENCE_ASYNC() asm volatile("fence.proxy.async.shared::cta;" ::: "memory")
#define NBAR(id, cnt) asm volatile("bar.sync %0, %1;" :: "r"(id), "r"(cnt) : "memory")
#define MBAR_WAIT(mb, ph) do { \
    uint32_t _m = (uint32_t)(mb); uint32_t _p = (uint32_t)(ph); uint32_t _d; \
    asm volatile("{\n\t.reg .pred p;\n\tmbarrier.try_wait.parity.acquire.cta.shared::cta.b64 p, [%1], %2;\n\tselp.b32 %0, 1, 0, p;\n\t}" \
        : "=r"(_d) : "r"(_m), "r"(_p) : "memory"); \
    if (!_d) { \
        asm volatile("{\n\t.reg .pred P1;\n\tWL_%=:\n\tmbarrier.try_wait.parity.acquire.cta.shared::cta.b64 P1, [%0], %1, 0x989680;\n\t@P1 bra.uni WD_%=;\n\tbra.uni WL_%=;\n\tWD_%=:\n\t}" \
            :: "r"(_m), "r"(_p) : "memory"); \
    } } while (0)
__device__ __forceinline__ void bulk_g2s(uint32_t dst, const void* src, uint32_t bytes, uint32_t mbar) {
    asm volatile("cp.async.bulk.shared::cta.global.mbarrier::complete_tx::bytes [%0], [%1], %2, [%3];"
        :: "r"(dst), "l"(src), "r"(bytes), "r"(mbar) : "memory");
}

// ---------------- merged prep: E repack + weight repack (one launch) ----------------
#define PE_N  (1536 * EPITCH)
#define WAB_N (12 * 320 * 72)
__global__ void kprep(const float* __restrict__ E,
                      const float* __restrict__ W1, const float* __restrict__ W2) {
    int idx = blockIdx.x * 256 + threadIdx.x;
    if (idx < PE_N) {
        int r = idx / EPITCH, pos = idx % EPITCH;
        int g = pos >> 3, wi = pos & 7, q = wi >> 1, h = wi & 1;
        int kw = g * 8 + q + 4 * h;
        uint32_t v = 0;
        if (kw < 384) {
            float2 e = *reinterpret_cast<const float2*>(E + (size_t)r * 768 + 2 * kw);
            v = packbf(e.x, e.y);
        }
        g_Ebf[idx] = v;
    } else if (idx < PE_N + WAB_N) {
        int t = idx - PE_N;
        int c = t / (320 * 72), rem = t % (320 * 72);
        int n = rem / 72, kk = rem % 72;
        float v = 0.f;
        if (kk < 64) {
            int kg = c * 64 + kk;
            if (n < 160) { if (n < HH) v = W1[(size_t)kg * HH + n]; }
            else { int h = n - 160; if (h < HH) v = W1[(size_t)(768 + kg) * HH + h]; }
        }
        g_wabT[t] = __float2bfloat16(v);
    } else if (idx < PE_N + WAB_N + W1C_WORDS + W2_WORDS) {
        int t = idx - PE_N - WAB_N;
        bool isW2 = (t >= W1C_WORDS);
        int r = isW2 ? (t - W1C_WORDS) : t;
        int ks = r / PKS, r1 = r % PKS;
        int lane = r1 / 44, r2 = r1 % 44;
        uint32_t v = 0;
        if (r2 < 40) {
            int nh = r2 / 20, r3 = r2 % 20, m = r3 / 4, e = r3 % 4;
            int gq = lane >> 2, qq = lane & 3;
            int nb = nh * 10 + 2 * m + (e >> 1);
            int kwl = ks * 8 + qq + (e & 1) * 4;
            int n = nb * 8 + gq;
            float v0 = 0.f, v1 = 0.f;
            if (n < HH) {
                int k0 = 2 * kwl;
                if (isW2) {
                    if (k0 < HH)     v0 = W2[(size_t)k0 * HH + n];
                    if (k0 + 1 < HH) v1 = W2[(size_t)(k0 + 1) * HH + n];
                } else {
                    v0 = W1[(size_t)(1536 + k0) * HH + n];
                    v1 = W1[(size_t)(1536 + k0 + 1) * HH + n];
                }
            }
            v = packbf(v0, v1);
        }
        if (isW2) g_w2P[r] = v; else g_w1cP[r] = v;
    }
}

// ---------------- k1: seeds GEMM -> g_A,g_B (pitch 152) ----------------
#define K1_E_BYTES (32 * EPITCH * 4)
#define K1_W_BYTES (320 * WABPITCH * 4)
#define K1_BAR_OFF (K1_E_BYTES + 2 * K1_W_BYTES)
#define K1_SMEM    (K1_BAR_OFF + 64)

__global__ __launch_bounds__(256, 1)
void k1_mma(const float* __restrict__ b1) {
    GDC_WAIT();      // kprep output fully visible
    GDC_LAUNCH();    // k2 may launch now (its own wait guards the seed dependency)

    extern __shared__ __align__(128) char smem[];
    uint32_t* sE = (uint32_t*)smem;
    uint32_t* sW[2] = { (uint32_t*)(smem + K1_E_BYTES),
                        (uint32_t*)(smem + K1_E_BYTES + K1_W_BYTES) };
    const uint32_t barE = smem_u32(smem + K1_BAR_OFF);
    const uint32_t barW[2] = { barE + 8, barE + 16 };
    const int tid = threadIdx.x, w = tid >> 5, lane = tid & 31;
    const int gq = lane >> 2, qq = lane & 3;
    const int r0 = blockIdx.x * 32;

    if (tid == 0) {
        MBAR_INIT(barE, 1); MBAR_INIT(barW[0], 1); MBAR_INIT(barW[1], 1);
        FENCE_ASYNC();
        MBAR_EXPECT_TX(barE, K1_E_BYTES);
        bulk_g2s(smem_u32(sE), g_Ebf + (size_t)r0 * EPITCH, K1_E_BYTES, barE);
        MBAR_EXPECT_TX(barW[0], K1_W_BYTES);
        bulk_g2s(smem_u32(sW[0]), g_wabT, K1_W_BYTES, barW[0]);
        MBAR_EXPECT_TX(barW[1], K1_W_BYTES);
        bulk_g2s(smem_u32(sW[1]), g_wabT + (size_t)320 * 72, K1_W_BYTES, barW[1]);
    }
    __syncthreads();
    MBAR_WAIT(barE, 0);

    float acc[2][5][4];
#pragma unroll
    for (int t = 0; t < 2; t++)
#pragma unroll
        for (int l = 0; l < 5; l++)
#pragma unroll
            for (int u = 0; u < 4; u++) acc[t][l][u] = 0.f;

    const uint32_t* e0p = sE + (size_t)gq * EPITCH;
    const uint32_t* e1p = e0p + 8 * EPITCH;
    const uint32_t* e2p = e0p + 16 * EPITCH;
    const uint32_t* e3p = e0p + 24 * EPITCH;

    for (int c = 0; c < 12; c++) {
        MBAR_WAIT(barW[c & 1], (c >> 1) & 1);
        const uint32_t* Wb = sW[c & 1];
#pragma unroll
        for (int ks = 0; ks < 4; ks++) {
            int kb = c * 32 + ks * 8 + 2 * qq;
            uint2 e0 = *(const uint2*)(e0p + kb);
            uint2 e1 = *(const uint2*)(e1p + kb);
            uint2 e2 = *(const uint2*)(e2p + kb);
            uint2 e3 = *(const uint2*)(e3p + kb);
            uint32_t a0[4] = { e0.x, e1.x, e0.y, e1.y };
            uint32_t a1[4] = { e2.x, e3.x, e2.y, e3.y };
#pragma unroll
            for (int l = 0; l < 5; l++) {
                int nrow = (w * 5 + l) * 8 + gq;
                uint32_t b[2] = { Wb[nrow * WABPITCH + ks * 8 + qq],
                                  Wb[nrow * WABPITCH + ks * 8 + qq + 4] };
                mma16816(acc[0][l], a0, b, acc[0][l]);
                mma16816(acc[1][l], a1, b, acc[1][l]);
            }
        }
        __syncthreads();
        if (tid == 0 && c + 2 < 12) {
            MBAR_EXPECT_TX(barW[c & 1], K1_W_BYTES);
            bulk_g2s(smem_u32(sW[c & 1]), g_wabT + (size_t)(c + 2) * 320 * 72,
                     K1_W_BYTES, barW[c & 1]);
        }
    }

#pragma unroll
    for (int t = 0; t < 2; t++)
#pragma unroll
        for (int l = 0; l < 5; l++) {
            int n0 = (w * 5 + l) * 8 + 2 * qq;
            int ra = r0 + 16 * t + gq, rb = ra + 8;
#pragma unroll
            for (int u = 0; u < 4; u++) {
                int row = (u < 2) ? ra : rb;
                int n = n0 + (u & 1);
                float v = acc[t][l][u];
                if (n < 160) { if (n < HH) g_A[(size_t)row * APITCH + n] = v + __ldg(b1 + n); }
                else { int h = n - 160; if (h < HH) g_B[(size_t)row * APITCH + h] = v; }
            }
        }
}

// ---------------- k2: fused pair MLP, 2 CTAs/SM, 4-deep W ring (round-9 config) ----------------
#define K2_EI_OFF   0                                  // 12*392*4 = 18816
#define K2_EJ_OFF   18816                              // 8*392*4  = 12544
#define K2_W_OFF    31360                              // 4 x 11264 = 45056
#define K2_H1_OFF   76416                              // 96*88*4 = 33792
#define K2_BW_OFF   110208                             // b2|W3: 1216
#define K2_BAR_OFF  111424
#define K2_SMEM     (K2_BAR_OFF + 128)                 // 111552

__global__ __launch_bounds__(192, 2)
void k2_mma(const float* __restrict__ b2,
            const float* __restrict__ W3) {
    const int bz = blockIdx.y;
    const int x = blockIdx.x;
    const int cumt[16] = {0,2,5,10,16,24,33,44,56,70,85,102,120,140,161,184};
    int ti = 0;
#pragma unroll
    for (int t = 1; t < 16; t++)
        if (cumt[t] <= x) ti = t;
    const int tj = x - cumt[ti];

    extern __shared__ __align__(128) char smem[];
    uint32_t* sEi = (uint32_t*)(smem + K2_EI_OFF);
    uint32_t* sEj = (uint32_t*)(smem + K2_EJ_OFF);
    uint32_t* sWr = (uint32_t*)(smem + K2_W_OFF);      // ring: 4 x SLAB_W
    uint32_t* sH1 = (uint32_t*)(smem + K2_H1_OFF);
    float*    sB2 = (float*)(smem + K2_BW_OFF);
    float*    sW3 = sB2 + 152;
    const uint32_t barE = smem_u32(smem + K2_BAR_OFF);
    const uint32_t barW0 = barE + 8;    // barW[b] = barW0 + 8b
    const uint32_t barC0 = barE + 40;   // barC[b] = barC0 + 8b
    const int tid = threadIdx.x, w = tid >> 5, lane = tid & 31;
    const int mh = w >> 1, nh = w & 1;
    const int gq = lane >> 2, qq = lane & 3;

    if (tid == 0) {
        MBAR_INIT(barE, 1);
#pragma unroll
        for (int b = 0; b < 4; b++) { MBAR_INIT(barW0 + 8 * b, 1); MBAR_INIT(barC0 + 8 * b, 6); }
        FENCE_ASYNC();
        MBAR_EXPECT_TX(barE, (12 + 8) * EPITCH * 4);
        bulk_g2s(smem_u32(sEi), g_Ebf + ((size_t)bz * 192 + ti * 12) * EPITCH, 12 * EPITCH * 4, barE);
        bulk_g2s(smem_u32(sEj), g_Ebf + ((size_t)bz * 192 + tj * 8) * EPITCH, 8 * EPITCH * 4, barE);
#pragma unroll
        for (int f = 0; f < 4; f++) {
            MBAR_EXPECT_TX(barW0 + 8 * f, SLAB_W * 4);
            bulk_g2s(smem_u32(sWr + f * SLAB_W), g_w1cP + (size_t)f * SLAB_W, SLAB_W * 4, barW0 + 8 * f);
        }
    }
    // stage b2/W3; zero sH1 pad words kw 76..79 (read by L2 ks9 against zero weights)
    for (int idx = tid; idx < 304; idx += 192) {
        if (idx < 152) sB2[idx] = (idx < HH) ? b2[idx] : 0.f;
        else { int h = idx - 152; sW3[h] = (h < HH) ? W3[h] : 0.f; }
    }
    for (int idx = tid; idx < 96 * 4; idx += 192)
        sH1[(idx >> 2) * H1PITCH + 76 + (idx & 3)] = 0;
    __syncthreads();
    MBAR_WAIT(barE, 0);

    float acc[2][10][4];
#pragma unroll
    for (int t = 0; t < 2; t++)
#pragma unroll
        for (int l = 0; l < 10; l++)
#pragma unroll
            for (int u = 0; u < 4; u++) acc[t][l][u] = 0.f;

    const uint32_t* eI0 = sEi + (size_t)(4 * mh + 0) * EPITCH;
    const uint32_t* eI1 = sEi + (size_t)(4 * mh + 1) * EPITCH;
    const uint32_t* eI2 = sEi + (size_t)(4 * mh + 2) * EPITCH;
    const uint32_t* eI3 = sEi + (size_t)(4 * mh + 3) * EPITCH;
    const uint32_t* eJp = sEj + (size_t)gq * EPITCH;
    const int bw_off = lane * 44 + nh * 20;
    const bool full_n = (nh == 0);   // nh==1 skips all-zero n-block 19

#define MMA_NBLOCKS(ACC, a0, a1, bp) do { \
        _Pragma("unroll") \
        for (int m = 0; m < 4; m++) { \
            uint4 bb = *(const uint4*)((bp) + m * 4); \
            uint32_t b0[2] = { bb.x, bb.y }; \
            uint32_t b1r[2] = { bb.z, bb.w }; \
            mma16816(ACC[0][2 * m],     a0, b0,  ACC[0][2 * m]); \
            mma16816(ACC[1][2 * m],     a1, b0,  ACC[1][2 * m]); \
            mma16816(ACC[0][2 * m + 1], a0, b1r, ACC[0][2 * m + 1]); \
            mma16816(ACC[1][2 * m + 1], a1, b1r, ACC[1][2 * m + 1]); \
        } \
        { \
            uint4 bb = *(const uint4*)((bp) + 16); \
            uint32_t b0[2] = { bb.x, bb.y }; \
            mma16816(ACC[0][8], a0, b0, ACC[0][8]); \
            mma16816(ACC[1][8], a1, b0, ACC[1][8]); \
            if (full_n) { \
                uint32_t b1r[2] = { bb.z, bb.w }; \
                mma16816(ACC[0][9], a0, b1r, ACC[0][9]); \
                mma16816(ACC[1][9], a1, b1r, ACC[1][9]); \
            } \
        } \
    } while (0)

    // ---- layer 1: 24 slabs of 2 k16-steps through the 4-buffer ring ----
    for (int f = 0; f < 24; f++) {
        const int buf = f & 3;
        const uint32_t bw = barW0 + 8 * buf, bc = barC0 + 8 * buf;
        MBAR_WAIT(bw, (f >> 2) & 1);
        const uint32_t* Wb = sWr + buf * SLAB_W;
#pragma unroll
        for (int ks = 0; ks < 2; ks++) {
            int kb = f * 16 + ks * 8 + 2 * qq;
            uint2 ej = *(const uint2*)(eJp + kb);
            uint2 e0 = *(const uint2*)(eI0 + kb);
            uint2 e1 = *(const uint2*)(eI1 + kb);
            uint2 e2 = *(const uint2*)(eI2 + kb);
            uint2 e3 = *(const uint2*)(eI3 + kb);
            uint32_t a0[4] = { bmul2(e0.x, ej.x), bmul2(e1.x, ej.x),
                               bmul2(e0.y, ej.y), bmul2(e1.y, ej.y) };
            uint32_t a1[4] = { bmul2(e2.x, ej.x), bmul2(e3.x, ej.x),
                               bmul2(e2.y, ej.y), bmul2(e3.y, ej.y) };
            const uint32_t* bp = Wb + ks * PKS + bw_off;
            MMA_NBLOCKS(acc, a0, a1, bp);
        }
        __syncwarp();
        if (lane == 0) MBAR_ARRIVE(bc);
        if (w == 0 && lane == 0) {
            MBAR_WAIT(bc, (f >> 2) & 1);
            int nf = f + 4;
            const uint32_t* src = (nf < 24) ? g_w1cP + (size_t)nf * SLAB_W
                                            : g_w2P + (size_t)(nf - 24) * SLAB_W;
            MBAR_EXPECT_TX(bw, SLAB_W * 4);
            bulk_g2s(smem_u32(sWr + buf * SLAB_W), src, SLAB_W * 4, bw);
        }
    }

    // ---- PDL: k1's seeds must be complete before epilogue 1 reads them ----
    GDC_WAIT();

    // ---- epilogue 1: + seeds (L2 gmem), ReLU, bf16 -> sH1 ----
    {
        const float* Bj = g_B + ((size_t)bz * 192 + tj * 8 + gq) * APITCH;
#pragma unroll
        for (int t = 0; t < 2; t++) {
            const float* A0 = g_A + ((size_t)bz * 192 + ti * 12 + 4 * mh + 2 * t) * APITCH;
            const float* A1 = A0 + APITCH;
#pragma unroll
            for (int l = 0; l < 10; l++) {
                if (l == 9 && !full_n) break;    // dead n-block; pad pre-zeroed
                int nbg = nh * 10 + l;
                int h0 = nbg * 8 + 2 * qq;
                float v0 = 0.f, v1 = 0.f, v2 = 0.f, v3 = 0.f;
                if (h0 < HH) {
                    float2 a0v = *(const float2*)(A0 + h0);
                    float2 a1v = *(const float2*)(A1 + h0);
                    float2 bjv = *(const float2*)(Bj + h0);
                    v0 = fmaxf(acc[t][l][0] + a0v.x + bjv.x, 0.f);
                    v1 = fmaxf(acc[t][l][1] + a0v.y + bjv.y, 0.f);
                    v2 = fmaxf(acc[t][l][2] + a1v.x + bjv.x, 0.f);
                    v3 = fmaxf(acc[t][l][3] + a1v.y + bjv.y, 0.f);
                }
                int kw = nbg * 4 + qq;
                int ilvw = ((kw >> 3) << 3) + 2 * (kw & 3) + ((kw >> 2) & 1);
                sH1[(32 * mh + 16 * t + gq) * H1PITCH + ilvw]     = packbf(v0, v1);
                sH1[(32 * mh + 16 * t + 8 + gq) * H1PITCH + ilvw] = packbf(v2, v3);
            }
        }
    }
    NBAR(1 + mh, 64);          // nh-pair exchange of h1 halves

    // ---- layer 2: K=160 = fetch slots f=24..28 (2 ks each) ----
    float ac2[2][10][4];
#pragma unroll
    for (int t = 0; t < 2; t++)
#pragma unroll
        for (int l = 0; l < 10; l++)
#pragma unroll
            for (int u = 0; u < 4; u++) ac2[t][l][u] = 0.f;

    const uint32_t* h0p = sH1 + (size_t)(32 * mh + gq) * H1PITCH;
    const uint32_t* h1p = h0p + 8 * H1PITCH;
    const uint32_t* h2p = h0p + 16 * H1PITCH;
    const uint32_t* h3p = h0p + 24 * H1PITCH;

#pragma unroll
    for (int f = 24; f < 29; f++) {
        const int buf = f & 3;
        const uint32_t bw = barW0 + 8 * buf, bc = barC0 + 8 * buf;
        MBAR_WAIT(bw, (f >> 2) & 1);
        const uint32_t* Wb = sWr + buf * SLAB_W;
#pragma unroll
        for (int ks2 = 0; ks2 < 2; ks2++) {
            int kb = (f - 24) * 16 + ks2 * 8 + 2 * qq;
            uint2 x0 = *(const uint2*)(h0p + kb);
            uint2 x1 = *(const uint2*)(h1p + kb);
            uint2 x2 = *(const uint2*)(h2p + kb);
            uint2 x3 = *(const uint2*)(h3p + kb);
            uint32_t a0[4] = { x0.x, x1.x, x0.y, x1.y };
            uint32_t a1[4] = { x2.x, x3.x, x2.y, x3.y };
            const uint32_t* bp = Wb + ks2 * PKS + bw_off;
            MMA_NBLOCKS(ac2, a0, a1, bp);
        }
        if (f == 24) {   // refill f=28 (W2 ks 8-9) into buf0 once all warps consumed f=24
            __syncwarp();
            if (lane == 0) MBAR_ARRIVE(bc);
            if (w == 0 && lane == 0) {
                MBAR_WAIT(bc, (f >> 2) & 1);
                MBAR_EXPECT_TX(bw, SLAB_W * 4);
                bulk_g2s(smem_u32(sWr + buf * SLAB_W), g_w2P + (size_t)4 * SLAB_W,
                         SLAB_W * 4, bw);
            }
        }
    }

    // ---- epilogue 2: +b2, ReLU, dot W3; partials to g_S / g_S2 (no exchange) ----
    float sp[2][2] = { {0.f, 0.f}, {0.f, 0.f} };
#pragma unroll
    for (int t = 0; t < 2; t++)
#pragma unroll
        for (int l = 0; l < 10; l++) {
            if (l == 9 && !full_n) break;
            int h0 = (nh * 10 + l) * 8 + 2 * qq;
            if (h0 < HH) {
                float2 bv = *(const float2*)(sB2 + h0);
                float2 wv = *(const float2*)(sW3 + h0);
                sp[t][0] += fmaxf(ac2[t][l][0] + bv.x, 0.f) * wv.x
                          + fmaxf(ac2[t][l][1] + bv.y, 0.f) * wv.y;
                sp[t][1] += fmaxf(ac2[t][l][2] + bv.x, 0.f) * wv.x
                          + fmaxf(ac2[t][l][3] + bv.y, 0.f) * wv.y;
            }
        }
#pragma unroll
    for (int t = 0; t < 2; t++)
#pragma unroll
        for (int s = 0; s < 2; s++) {
            sp[t][s] += __shfl_xor_sync(0xffffffffu, sp[t][s], 1);
            sp[t][s] += __shfl_xor_sync(0xffffffffu, sp[t][s], 2);
        }
    if (qq == 0) {
        float* dst = full_n ? g_S2 : g_S;
#pragma unroll
        for (int t = 0; t < 2; t++)
#pragma unroll
            for (int s = 0; s < 2; s++) {
                int r = 32 * mh + 16 * t + 8 * s + gq;
                int ip = ti * 12 + (r >> 3), jp = tj * 8 + (r & 7);
                if (jp < ip)
                    dst[((size_t)bz * 192 + ip) * 192 + jp] = sp[t][s];
            }
    }
}

// ---------------- k3: warp-per-row tril softmax (barrier-free) ----------------
__global__ __launch_bounds__(256, 4)
void k3_softmax(float* __restrict__ out, const float* __restrict__ b3) {
    GDC_WAIT();   // k2's scores complete
    const int w = threadIdx.x >> 5, lane = threadIdx.x & 31;
    const int row = blockIdx.x * 8 + w;            // 0..1535
    const int ii = row - (row / 192) * 192;
    const float b3v = __ldg(b3);

    float v[6];
    float m = -1e30f;
#pragma unroll
    for (int k = 0; k < 6; k++) {
        int j = lane + 32 * k;
        float val;
        if (j < ii) {
            size_t idx = (size_t)row * 192 + j;
            val = g_S[idx] + g_S2[idx] + b3v;
        } else if (j == ii) val = 0.f;
        else                val = -1e30f;
        v[k] = val;
        m = fmaxf(m, val);
    }
#pragma unroll
    for (int o = 16; o; o >>= 1) m = fmaxf(m, __shfl_xor_sync(0xffffffffu, m, o));

    float s = 0.f;
#pragma unroll
    for (int k = 0; k < 6; k++) {
        int j = lane + 32 * k;
        v[k] = (j <= ii) ? expf(v[k] - m) : 0.f;
        s += v[k];
    }
#pragma unroll
    for (int o = 16; o; o >>= 1) s += __shfl_xor_sync(0xffffffffu, s, o);
    float inv = 1.f / s;

#pragma unroll
    for (int k = 0; k < 6; k++) {
        int j = lane + 32 * k;
        out[(size_t)row * 192 + j] = (j <= ii) ? (v[k] * inv) : -1000.0f;
    }
}

// ---------------------------------------------------------------------------
extern "C" void kernel_launch(void* const* d_in, const int* in_sizes, int n_in,
                              void* d_out, int out_size) {
    const float* E  = (const float*)d_in[0];
    const float* W1 = (const float*)d_in[1];
    const float* b1 = (const float*)d_in[2];
    const float* W2 = (const float*)d_in[3];
    const float* b2 = (const float*)d_in[4];
    const float* W3 = (const float*)d_in[5];
    const float* b3 = (const float*)d_in[6];
    float* out = (float*)d_out;

    cudaFuncSetAttribute(k1_mma, cudaFuncAttributeMaxDynamicSharedMemorySize, K1_SMEM);
    cudaFuncSetAttribute(k2_mma, cudaFuncAttributeMaxDynamicSharedMemorySize, K2_SMEM);

    const int prep_n = PE_N + WAB_N + W1C_WORDS + W2_WORDS;
    kprep<<<(prep_n + 255) / 256, 256>>>(E, W1, W2);

    cudaLaunchAttribute pdl[1];
    pdl[0].id = cudaLaunchAttributeProgrammaticStreamSerialization;
    pdl[0].val.programmaticStreamSerializationAllowed = 1;

    {   // k1 (PDL dependent of kprep; waits at start)
        cudaLaunchConfig_t cfg = {};
        cfg.gridDim = dim3(48); cfg.blockDim = dim3(256);
        cfg.dynamicSmemBytes = K1_SMEM;
        cfg.attrs = pdl; cfg.numAttrs = 1;
        cudaLaunchKernelEx(&cfg, k1_mma, b1);
    }
    {   // k2 (PDL dependent of k1; k1 triggers at its start, k2 waits before epilogue 1)
        cudaLaunchConfig_t cfg = {};
        cfg.gridDim = dim3(208, 8); cfg.blockDim = dim3(192);
        cfg.dynamicSmemBytes = K2_SMEM;
        cfg.attrs = pdl; cfg.numAttrs = 1;
        cudaLaunchKernelEx(&cfg, k2_mma, b2, W3);
    }
    {   // k3 (PDL dependent of k2; waits at start)
        cudaLaunchConfig_t cfg = {};
        cfg.gridDim = dim3(192); cfg.blockDim = dim3(256);
        cfg.attrs = pdl; cfg.numAttrs = 1;
        cudaLaunchKernelEx(&cfg, k3_softmax, out, b3);
    }
}